// round 2
// baseline (speedup 1.0000x reference)
#include <cuda_runtime.h>
#include <math.h>
#include <stdint.h>

#define BATCH 64
#define NPRI 192
#define SP 36
#define CF 64
#define HID 192
#define GRP 6
#define HD 32
#define M_ROWS (BATCH*NPRI)   /* 12288 */
#define PRI_DIM 76
#define OUT_COLS 76

/* ------------------------- scratch (static device) ------------------------- */
__device__ float g_nhwc0[BATCH*10*25*CF];
__device__ float g_nhwc1[BATCH*20*50*CF];
__device__ float g_nhwc2[BATCH*40*100*CF];
__device__ float g_feature[(size_t)M_ROWS*SP*CF];   /* (m, s, c) 113MB */
__device__ float g_feat[M_ROWS*HID];
__device__ float g_q[M_ROWS*HID];
__device__ float g_ctx[M_ROWS*HID];
__device__ float g_h[M_ROWS*2*HID];
__device__ float g_fc[M_ROWS*HID];
__device__ float g_clsf[M_ROWS*HID];
__device__ float g_regf[M_ROWS*HID];

/* ------------------------- NCHW -> NHWC transpose ------------------------- */
__global__ void transpose_k(const float* __restrict__ in, float* __restrict__ out,
                            int C, int HW) {
    __shared__ float tile[32][33];
    int b  = blockIdx.z;
    int p0 = blockIdx.x * 32;
    int c0 = blockIdx.y * 32;
    const float* inb = in  + (size_t)b * C * HW;
    float*       outb = out + (size_t)b * C * HW;
    for (int i = threadIdx.y; i < 32; i += 8) {
        int c = c0 + i, p = p0 + threadIdx.x;
        tile[i][threadIdx.x] = (p < HW) ? inb[(size_t)c * HW + p] : 0.f;
    }
    __syncthreads();
    for (int i = threadIdx.y; i < 32; i += 8) {
        int p = p0 + i, c = c0 + threadIdx.x;
        if (p < HW) outb[(size_t)p * C + c] = tile[threadIdx.x][i];
    }
}

/* ------------------------- bilinear sampling ------------------------- */
__device__ __forceinline__ float bilin(const float* __restrict__ f, int b, int H, int W,
                                       float px, float py, int c) {
    float gx = px * 2.f - 1.f, gy = py * 2.f - 1.f;
    float x = (gx + 1.f) * 0.5f * (float)(W - 1);
    float y = (gy + 1.f) * 0.5f * (float)(H - 1);
    float x0f = floorf(x), y0f = floorf(y);
    float wx1 = x - x0f, wy1 = y - y0f;
    int x0 = (int)x0f, y0 = (int)y0f;
    const float* fb = f + (size_t)b * H * W * CF + c;
    float w00 = (1.f - wx1) * (1.f - wy1);
    float w10 = wx1 * (1.f - wy1);
    float w01 = (1.f - wx1) * wy1;
    float w11 = wx1 * wy1;
    float v = 0.f;
    bool xv0 = (x0 >= 0) && (x0 < W);
    bool xv1 = (x0 + 1 >= 0) && (x0 + 1 < W);
    bool yv0 = (y0 >= 0) && (y0 < H);
    bool yv1 = (y0 + 1 >= 0) && (y0 + 1 < H);
    if (xv0 && yv0) v += w00 * fb[((size_t)y0 * W + x0) * CF];
    if (xv1 && yv0) v += w10 * fb[((size_t)y0 * W + x0 + 1) * CF];
    if (xv0 && yv1) v += w01 * fb[((size_t)(y0 + 1) * W + x0) * CF];
    if (xv1 && yv1) v += w11 * fb[((size_t)(y0 + 1) * W + x0 + 1) * CF];
    return v;
}

/* one thread = one (b,n,s,c); block = (64 channels, 4 sample points) */
__global__ void sample_k(const float* __restrict__ priors, const float* __restrict__ z_emb) {
    int c = threadIdx.x;
    int s = blockIdx.x * 4 + threadIdx.y;
    int n = blockIdx.y, b = blockIdx.z;
    int m = b * NPRI + n;
    int j = 35 - s;
    int idxj = (71 * j) / 35;                 /* exact match of linspace*71 floor */
    float px = priors[(size_t)m * PRI_DIM + 4 + idxj];
    float py = 1.0f - (float)idxj / 71.0f;
    float e = z_emb[s];
    float w0 = expf(-(e - 0.f) * (e - 0.f) * 0.5f);
    float w1 = expf(-(e - 1.f) * (e - 1.f) * 0.5f);
    float w2 = expf(-(e - 2.f) * (e - 2.f) * 0.5f);
    float inv = 1.f / (w0 + w1 + w2);
    float acc = w0 * inv * bilin(g_nhwc0, b, 10, 25, px, py, c)
              + w1 * inv * bilin(g_nhwc1, b, 20, 50, px, py, c)
              + w2 * inv * bilin(g_nhwc2, b, 40, 100, px, py, c);
    g_feature[(size_t)m * (SP * CF) + s * CF + c] = acc;
}

/* ------------------------- generic tiled fp32 GEMM ------------------------- */
/* C[M,N] = act(A[M,K] @ B + bias) (+ res). B row-major (K,N) or (N,K) if TRANSB.
 * If GATHER: blockIdx.y is the group index g; pointers are offset per group. */
template<int BM, int BN, int BK, bool TRANSB, bool BIAS, bool RELU, bool RES, bool GATHER>
__global__ void gemm_k(const float* __restrict__ A, const float* __restrict__ B,
                       const float* __restrict__ bias, const float* __restrict__ res,
                       float* __restrict__ C,
                       int M, int N, int K, int lda, int ldb, int ldc) {
    constexpr int TM = 4, TN = 4;
    constexpr int THREADS = (BM / TM) * (BN / TN);
    __shared__ float As[BK][BM];
    __shared__ float Bs[BK][BN];
    const int tid = threadIdx.x;
    const int tn = tid % (BN / TN);
    const int tm = tid / (BN / TN);
    const int row0 = blockIdx.x * BM;
    int col0;
    if (GATHER) {
        int g = blockIdx.y;
        A    += (size_t)g * K;            /* group slice of feature row */
        B    += (size_t)g * BN * K;       /* gather_w rows for this group */
        bias += g * BN;
        C    += g * BN;
        col0 = 0;
    } else {
        col0 = blockIdx.y * BN;
    }
    float acc[TM][TN];
#pragma unroll
    for (int i = 0; i < TM; i++)
#pragma unroll
        for (int jj = 0; jj < TN; jj++) acc[i][jj] = 0.f;

    for (int k0 = 0; k0 < K; k0 += BK) {
        for (int i = tid; i < BM * (BK / 4); i += THREADS) {
            int r = i / (BK / 4), c4 = i % (BK / 4);
            float4 v = *(const float4*)(A + (size_t)(row0 + r) * lda + k0 + c4 * 4);
            As[c4 * 4 + 0][r] = v.x; As[c4 * 4 + 1][r] = v.y;
            As[c4 * 4 + 2][r] = v.z; As[c4 * 4 + 3][r] = v.w;
        }
        if (!TRANSB) {
            for (int i = tid; i < BK * (BN / 4); i += THREADS) {
                int r = i / (BN / 4), c4 = i % (BN / 4);
                *(float4*)&Bs[r][c4 * 4] =
                    *(const float4*)(B + (size_t)(k0 + r) * ldb + col0 + c4 * 4);
            }
        } else {
            for (int i = tid; i < BN * (BK / 4); i += THREADS) {
                int nn = i / (BK / 4), c4 = i % (BK / 4);
                float4 v = *(const float4*)(B + (size_t)(nn) * ldb + k0 + c4 * 4);
                Bs[c4 * 4 + 0][nn] = v.x; Bs[c4 * 4 + 1][nn] = v.y;
                Bs[c4 * 4 + 2][nn] = v.z; Bs[c4 * 4 + 3][nn] = v.w;
            }
        }
        __syncthreads();
#pragma unroll
        for (int k = 0; k < BK; k++) {
            float4 a4 = *(const float4*)&As[k][tm * TM];
            float4 b4 = *(const float4*)&Bs[k][tn * TN];
            float a[4] = {a4.x, a4.y, a4.z, a4.w};
            float bb[4] = {b4.x, b4.y, b4.z, b4.w};
#pragma unroll
            for (int i = 0; i < TM; i++)
#pragma unroll
                for (int jj = 0; jj < TN; jj++) acc[i][jj] += a[i] * bb[jj];
        }
        __syncthreads();
    }
#pragma unroll
    for (int i = 0; i < TM; i++) {
        int r = row0 + tm * TM + i;
#pragma unroll
        for (int jj = 0; jj < TN; jj++) {
            int cc = col0 + tn * TN + jj;
            float v = acc[i][jj];
            if (BIAS) v += bias[cc];
            if (RELU) v = fmaxf(v, 0.f);
            if (RES)  v += res[(size_t)r * ldc + cc];
            C[(size_t)r * ldc + cc] = v;
        }
    }
}

/* ------------------------- per-(b,g) attention, flash-style -------------------------
 * s = scale * q . (kx @ k_w)  ==  (scale * k_w^T q) . kx  -> only kx tile in smem. */
__global__ __launch_bounds__(192) void attn_k(const float* __restrict__ k_w) {
    int g = blockIdx.x, b = blockIdx.y;
    __shared__ float kx_s[NPRI * HD];     /* 24 KB */
    int tid = threadIdx.x;                /* 0..191 = query index */
    for (int i = tid; i < NPRI * HD; i += 192) {
        int n = i / HD, d = i % HD;
        kx_s[i] = g_feat[(size_t)(b * NPRI + n) * HID + g * HD + d];
    }
    __syncthreads();

    float qt[HD];
    {
        float qr[HD];
#pragma unroll
        for (int d = 0; d < HD; d++)
            qr[d] = g_q[(size_t)(b * NPRI + tid) * HID + g * HD + d];
#pragma unroll
        for (int e = 0; e < HD; e++) {
            float s = 0.f;
#pragma unroll
            for (int d = 0; d < HD; d++) s += k_w[e * HD + d] * qr[d];
            qt[e] = s * 0.17677669529663687f;   /* 32^-0.5 */
        }
    }
    float acc[HD];
#pragma unroll
    for (int d = 0; d < HD; d++) acc[d] = 0.f;
    float mx = -INFINITY, ls = 0.f;
    for (int mkey = 0; mkey < NPRI; mkey++) {
        const float* kr = &kx_s[mkey * HD];
        float s = 0.f;
#pragma unroll
        for (int e = 0; e < HD; e++) s += qt[e] * kr[e];
        float mn = fmaxf(mx, s);
        float corr = expf(mx - mn);
        float p = expf(s - mn);
        ls = ls * corr + p;
#pragma unroll
        for (int d = 0; d < HD; d++) acc[d] = acc[d] * corr + p * kr[d];
        mx = mn;
    }
    float inv = 1.f / ls;
#pragma unroll
    for (int d = 0; d < HD; d++)
        g_ctx[(size_t)(b * NPRI + tid) * HID + g * HD + d] = acc[d] * inv;
}

/* ------------------------- final heads + output assembly ------------------------- */
__global__ void head_k(const float* __restrict__ cls_w, const float* __restrict__ cls_b,
                       const float* __restrict__ reg_w, const float* __restrict__ reg_b,
                       const float* __restrict__ priors, float* __restrict__ out) {
    __shared__ float sc[3][HID], sr[3][HID];
    int m0 = blockIdx.x * 3;
    int tid = threadIdx.y * 76 + threadIdx.x;
    for (int i = tid; i < 3 * HID; i += 228) {
        int r = i / HID, c = i % HID;
        sc[r][c] = g_clsf[(size_t)(m0 + r) * HID + c];
        sr[r][c] = g_regf[(size_t)(m0 + r) * HID + c];
    }
    __syncthreads();
    int r = threadIdx.y, col = threadIdx.x;
    int m = m0 + r;
    float v;
    if (col < 2) {
        v = cls_b[col];
        for (int e = 0; e < HID; e++) v += sc[r][e] * cls_w[e * 2 + col];
    } else {
        int jj = col - 2;
        v = reg_b[jj] + priors[(size_t)m * PRI_DIM + col];
        for (int e = 0; e < HID; e++) v += sr[r][e] * reg_w[e * 74 + jj];
    }
    out[(size_t)m * OUT_COLS + col] = v;
}

/* ------------------------- host driver ------------------------- */
extern "C" void kernel_launch(void* const* d_in, const int* in_sizes, int n_in,
                              void* d_out, int out_size) {
    const float* feat0   = (const float*)d_in[0];
    const float* feat1   = (const float*)d_in[1];
    const float* feat2   = (const float*)d_in[2];
    const float* priors  = (const float*)d_in[3];
    const float* z_emb   = (const float*)d_in[4];
    const float* gather_w= (const float*)d_in[5];
    const float* gather_b= (const float*)d_in[6];
    const float* q_w     = (const float*)d_in[7];
    const float* k_w     = (const float*)d_in[8];
    const float* ch_w1   = (const float*)d_in[9];
    const float* ch_b1   = (const float*)d_in[10];
    const float* ch_w2   = (const float*)d_in[11];
    const float* ch_b2   = (const float*)d_in[12];
    const float* reg_m_w = (const float*)d_in[13];
    const float* reg_m_b = (const float*)d_in[14];
    const float* cls_m_w = (const float*)d_in[15];
    const float* cls_m_b = (const float*)d_in[16];
    const float* reg_w   = (const float*)d_in[17];
    const float* reg_b   = (const float*)d_in[18];
    const float* cls_w   = (const float*)d_in[19];
    const float* cls_b   = (const float*)d_in[20];
    float* out = (float*)d_out;

    float *p_nhwc0, *p_nhwc1, *p_nhwc2, *p_feature, *p_feat, *p_q, *p_ctx, *p_h,
          *p_fc, *p_clsf, *p_regf;
    cudaGetSymbolAddress((void**)&p_nhwc0, g_nhwc0);
    cudaGetSymbolAddress((void**)&p_nhwc1, g_nhwc1);
    cudaGetSymbolAddress((void**)&p_nhwc2, g_nhwc2);
    cudaGetSymbolAddress((void**)&p_feature, g_feature);
    cudaGetSymbolAddress((void**)&p_feat, g_feat);
    cudaGetSymbolAddress((void**)&p_q, g_q);
    cudaGetSymbolAddress((void**)&p_ctx, g_ctx);
    cudaGetSymbolAddress((void**)&p_h, g_h);
    cudaGetSymbolAddress((void**)&p_fc, g_fc);
    cudaGetSymbolAddress((void**)&p_clsf, g_clsf);
    cudaGetSymbolAddress((void**)&p_regf, g_regf);

    dim3 tb(32, 8);
    transpose_k<<<dim3(8,   2, BATCH), tb>>>(feat0, p_nhwc0, 64, 250);
    transpose_k<<<dim3(32,  2, BATCH), tb>>>(feat1, p_nhwc1, 64, 1000);
    transpose_k<<<dim3(125, 2, BATCH), tb>>>(feat2, p_nhwc2, 64, 4000);

    sample_k<<<dim3(9, NPRI, BATCH), dim3(64, 4)>>>(priors, z_emb);

    /* gather_fc: single launch, gridDim.y = group */
    gemm_k<64, 32, 32, true, true, false, false, true><<<dim3(M_ROWS / 64, GRP), 128>>>(
        p_feature, gather_w, gather_b, nullptr, p_feat,
        M_ROWS, 32, 384, SP * CF, 384, HID);

    /* q = feat @ q_w */
    gemm_k<64, 64, 32, false, false, false, false, false><<<dim3(M_ROWS / 64, 3), 256>>>(
        p_feat, q_w, nullptr, nullptr, p_q, M_ROWS, HID, HID, HID, HID, HID);

    attn_k<<<dim3(GRP, BATCH), 192>>>(k_w);

    /* channel MLP: h = relu(ctx @ ch_w1 + b1); fc = feat + h @ ch_w2 + b2 */
    gemm_k<64, 64, 32, false, true, true, false, false><<<dim3(M_ROWS / 64, 6), 256>>>(
        p_ctx, ch_w1, ch_b1, nullptr, p_h, M_ROWS, 2 * HID, HID, HID, 2 * HID, 2 * HID);
    gemm_k<64, 64, 32, false, true, false, true, false><<<dim3(M_ROWS / 64, 3), 256>>>(
        p_h, ch_w2, ch_b2, p_feat, p_fc, M_ROWS, HID, 2 * HID, 2 * HID, HID, HID);

    /* heads */
    gemm_k<64, 64, 32, false, true, true, false, false><<<dim3(M_ROWS / 64, 3), 256>>>(
        p_fc, cls_m_w, cls_m_b, nullptr, p_clsf, M_ROWS, HID, HID, HID, HID, HID);
    gemm_k<64, 64, 32, false, true, true, false, false><<<dim3(M_ROWS / 64, 3), 256>>>(
        p_fc, reg_m_w, reg_m_b, nullptr, p_regf, M_ROWS, HID, HID, HID, HID, HID);

    head_k<<<M_ROWS / 3, dim3(76, 3)>>>(cls_w, cls_b, reg_w, reg_b, priors, out);
}

// round 4
// speedup vs baseline: 1.1252x; 1.1252x over previous
#include <cuda_runtime.h>
#include <math.h>
#include <stdint.h>

#define BATCH 64
#define NPRI 192
#define SP 36
#define CF 64
#define HID 192
#define GRP 6
#define HD 32
#define M_ROWS (BATCH*NPRI)   /* 12288 */
#define PRI_DIM 76
#define OUT_COLS 76
#define MS (M_ROWS*SP)        /* 442368 (m,s) pairs */

/* ------------------------- scratch (static device) ------------------------- */
__device__ float g_nhwc0[BATCH*10*25*CF];
__device__ float g_nhwc1[BATCH*20*50*CF];
__device__ float g_nhwc2[BATCH*40*100*CF];
__device__ int   g_meta[(size_t)MS*24];             /* per (m,s): 3 lvl x (4 idx + 4 w) */
__device__ float g_feature[(size_t)MS*CF];          /* (m, s, c) 113MB */
__device__ float g_feat[M_ROWS*HID];
__device__ float g_q[M_ROWS*HID];
__device__ float g_ctx[M_ROWS*HID];
__device__ float g_h[M_ROWS*2*HID];
__device__ float g_fc[M_ROWS*HID];
__device__ float g_clsf[M_ROWS*HID];
__device__ float g_regf[M_ROWS*HID];

/* ------------------------- NCHW -> NHWC transpose ------------------------- */
__global__ void transpose_k(const float* __restrict__ in, float* __restrict__ out,
                            int C, int HW) {
    __shared__ float tile[32][33];
    int b  = blockIdx.z;
    int p0 = blockIdx.x * 32;
    int c0 = blockIdx.y * 32;
    const float* inb = in  + (size_t)b * C * HW;
    float*       outb = out + (size_t)b * C * HW;
    for (int i = threadIdx.y; i < 32; i += 8) {
        int c = c0 + i, p = p0 + threadIdx.x;
        tile[i][threadIdx.x] = (p < HW) ? inb[(size_t)c * HW + p] : 0.f;
    }
    __syncthreads();
    for (int i = threadIdx.y; i < 32; i += 8) {
        int p = p0 + i, c = c0 + threadIdx.x;
        if (p < HW) outb[(size_t)p * C + c] = tile[threadIdx.x][i];
    }
}

/* ------------------------- sampling metadata: one thread per (m,s) ------------------------- */
__global__ void meta_k(const float* __restrict__ priors, const float* __restrict__ z_emb) {
    int t = blockIdx.x * 256 + threadIdx.x;
    if (t >= MS) return;
    int m = t / SP, s = t % SP;
    int j = 35 - s;
    int idxj = (71 * j) / 35;                     /* = SAMPLE_X_IDX[35-s] */
    float px = priors[(size_t)m * PRI_DIM + 4 + idxj];
    float py = 1.0f - (float)idxj / 71.0f;
    float e = z_emb[s];
    float w0 = expf(-e * e * 0.5f);
    float w1 = expf(-(e - 1.f) * (e - 1.f) * 0.5f);
    float w2 = expf(-(e - 2.f) * (e - 2.f) * 0.5f);
    float inv = 1.f / (w0 + w1 + w2);
    float zw[3] = {w0 * inv, w1 * inv, w2 * inv};
    const int Hs[3] = {10, 20, 40}, Ws[3] = {25, 50, 100};
    int* out = g_meta + (size_t)t * 24;
#pragma unroll
    for (int lvl = 0; lvl < 3; lvl++) {
        int W = Ws[lvl], H = Hs[lvl];
        /* (gx+1)*0.5*(W-1) with gx = px*2-1  ==  px*(W-1) */
        float x = px * (float)(W - 1);
        float y = py * (float)(H - 1);
        float x0f = floorf(x), y0f = floorf(y);
        float wx = x - x0f, wy = y - y0f;
        int x0 = (int)x0f, y0 = (int)y0f;
        bool xv0 = (x0 >= 0) && (x0 < W);
        bool xv1 = (x0 + 1 >= 0) && (x0 + 1 < W);
        bool yv0 = (y0 >= 0) && (y0 < H);
        bool yv1 = (y0 + 1 >= 0) && (y0 + 1 < H);
        int xc0 = min(max(x0, 0), W - 1);
        int xc1 = min(max(x0 + 1, 0), W - 1);
        int yc0 = min(max(y0, 0), H - 1);
        int yc1 = min(max(y0 + 1, 0), H - 1);
        float zl = zw[lvl];
        out[lvl * 8 + 0] = (yc0 * W + xc0) * CF;
        out[lvl * 8 + 1] = (yc0 * W + xc1) * CF;
        out[lvl * 8 + 2] = (yc1 * W + xc0) * CF;
        out[lvl * 8 + 3] = (yc1 * W + xc1) * CF;
        out[lvl * 8 + 4] = __float_as_int((1.f - wx) * (1.f - wy) * zl * (float)(xv0 && yv0));
        out[lvl * 8 + 5] = __float_as_int(wx * (1.f - wy) * zl * (float)(xv1 && yv0));
        out[lvl * 8 + 6] = __float_as_int((1.f - wx) * wy * zl * (float)(xv0 && yv1));
        out[lvl * 8 + 7] = __float_as_int(wx * wy * zl * (float)(xv1 && yv1));
    }
}

/* ------------------------- weighted gather: one warp per (m,s), lane = channel pair ---- */
__global__ __launch_bounds__(256) void gather_k() {
    int w = blockIdx.x * 8 + threadIdx.y;         /* (m,s) index */
    int lane = threadIdx.x;
    int m = w / SP;
    int b = m / NPRI;
    const int* meta = g_meta + (size_t)w * 24;
    const float* base0 = g_nhwc0 + (size_t)b * 10 * 25 * CF + 2 * lane;
    const float* base1 = g_nhwc1 + (size_t)b * 20 * 50 * CF + 2 * lane;
    const float* base2 = g_nhwc2 + (size_t)b * 40 * 100 * CF + 2 * lane;
    float ax = 0.f, ay = 0.f;
#pragma unroll
    for (int lvl = 0; lvl < 3; lvl++) {
        const float* fb = (lvl == 0) ? base0 : (lvl == 1) ? base1 : base2;
        int i0 = meta[lvl * 8 + 0], i1 = meta[lvl * 8 + 1];
        int i2 = meta[lvl * 8 + 2], i3 = meta[lvl * 8 + 3];
        float w0 = __int_as_float(meta[lvl * 8 + 4]);
        float w1 = __int_as_float(meta[lvl * 8 + 5]);
        float w2 = __int_as_float(meta[lvl * 8 + 6]);
        float w3 = __int_as_float(meta[lvl * 8 + 7]);
        float2 v0 = *(const float2*)(fb + i0);
        float2 v1 = *(const float2*)(fb + i1);
        float2 v2 = *(const float2*)(fb + i2);
        float2 v3 = *(const float2*)(fb + i3);
        ax += w0 * v0.x + w1 * v1.x + w2 * v2.x + w3 * v3.x;
        ay += w0 * v0.y + w1 * v1.y + w2 * v2.y + w3 * v3.y;
    }
    float2 r; r.x = ax; r.y = ay;
    *(float2*)(g_feature + (size_t)w * CF + 2 * lane) = r;
}

/* ------------------------- generic tiled fp32 GEMM ------------------------- */
/* C[M,N] = act(A[M,K] @ B + bias) (+ res). B row-major (K,N) or (N,K) if TRANSB.
 * GATHER: blockIdx.y = group g; pointers offset per group.
 * DUAL:   blockIdx.y in [0,2*NYH): lower half -> (B,bias,C), upper -> (B2,bias2,C2). */
template<int BM, int BN, int BK, bool TRANSB, bool BIAS, bool RELU, bool RES, bool GATHER, bool DUAL>
__global__ void gemm_k(const float* __restrict__ A, const float* __restrict__ B,
                       const float* __restrict__ bias, const float* __restrict__ res,
                       float* __restrict__ C,
                       int M, int N, int K, int lda, int ldb, int ldc,
                       const float* __restrict__ B2 = nullptr,
                       const float* __restrict__ bias2 = nullptr,
                       float* __restrict__ C2 = nullptr) {
    constexpr int TM = 4, TN = 4;
    constexpr int THREADS = (BM / TM) * (BN / TN);
    __shared__ float As[BK][BM];
    __shared__ float Bs[BK][BN];
    const int tid = threadIdx.x;
    const int tn = tid % (BN / TN);
    const int tm = tid / (BN / TN);
    const int row0 = blockIdx.x * BM;
    int col0;
    if (GATHER) {
        int g = blockIdx.y;
        A    += (size_t)g * K;
        B    += (size_t)g * BN * K;
        bias += g * BN;
        C    += g * BN;
        col0 = 0;
    } else if (DUAL) {
        int half = gridDim.y / 2;
        int y = blockIdx.y;
        if (y >= half) { B = B2; bias = bias2; C = C2; y -= half; }
        col0 = y * BN;
    } else {
        col0 = blockIdx.y * BN;
    }
    float acc[TM][TN];
#pragma unroll
    for (int i = 0; i < TM; i++)
#pragma unroll
        for (int jj = 0; jj < TN; jj++) acc[i][jj] = 0.f;

    for (int k0 = 0; k0 < K; k0 += BK) {
        for (int i = tid; i < BM * (BK / 4); i += THREADS) {
            int r = i / (BK / 4), c4 = i % (BK / 4);
            float4 v = *(const float4*)(A + (size_t)(row0 + r) * lda + k0 + c4 * 4);
            As[c4 * 4 + 0][r] = v.x; As[c4 * 4 + 1][r] = v.y;
            As[c4 * 4 + 2][r] = v.z; As[c4 * 4 + 3][r] = v.w;
        }
        if (!TRANSB) {
            for (int i = tid; i < BK * (BN / 4); i += THREADS) {
                int r = i / (BN / 4), c4 = i % (BN / 4);
                *(float4*)&Bs[r][c4 * 4] =
                    *(const float4*)(B + (size_t)(k0 + r) * ldb + col0 + c4 * 4);
            }
        } else {
            for (int i = tid; i < BN * (BK / 4); i += THREADS) {
                int nn = i / (BK / 4), c4 = i % (BK / 4);
                float4 v = *(const float4*)(B + (size_t)(nn) * ldb + k0 + c4 * 4);
                Bs[c4 * 4 + 0][nn] = v.x; Bs[c4 * 4 + 1][nn] = v.y;
                Bs[c4 * 4 + 2][nn] = v.z; Bs[c4 * 4 + 3][nn] = v.w;
            }
        }
        __syncthreads();
#pragma unroll
        for (int k = 0; k < BK; k++) {
            float4 a4 = *(const float4*)&As[k][tm * TM];
            float4 b4 = *(const float4*)&Bs[k][tn * TN];
            float a[4] = {a4.x, a4.y, a4.z, a4.w};
            float bb[4] = {b4.x, b4.y, b4.z, b4.w};
#pragma unroll
            for (int i = 0; i < TM; i++)
#pragma unroll
                for (int jj = 0; jj < TN; jj++) acc[i][jj] += a[i] * bb[jj];
        }
        __syncthreads();
    }
#pragma unroll
    for (int i = 0; i < TM; i++) {
        int r = row0 + tm * TM + i;
#pragma unroll
        for (int jj = 0; jj < TN; jj++) {
            int cc = col0 + tn * TN + jj;
            float v = acc[i][jj];
            if (BIAS) v += bias[cc];
            if (RELU) v = fmaxf(v, 0.f);
            if (RES)  v += res[(size_t)r * ldc + cc];
            C[(size_t)r * ldc + cc] = v;
        }
    }
}

/* ------------------------- per-(b,g) attention, flash-style -------------------------
 * s = scale * q . (kx @ k_w)  ==  (scale * k_w^T q) . kx  -> only kx tile in smem. */
__global__ __launch_bounds__(192) void attn_k(const float* __restrict__ k_w) {
    int g = blockIdx.x, b = blockIdx.y;
    __shared__ float kx_s[NPRI * HD];     /* 24 KB */
    int tid = threadIdx.x;                /* 0..191 = query index */
    for (int i = tid; i < NPRI * HD; i += 192) {
        int n = i / HD, d = i % HD;
        kx_s[i] = g_feat[(size_t)(b * NPRI + n) * HID + g * HD + d];
    }
    __syncthreads();

    float qt[HD];
    {
        float qr[HD];
#pragma unroll
        for (int d = 0; d < HD; d++)
            qr[d] = g_q[(size_t)(b * NPRI + tid) * HID + g * HD + d];
#pragma unroll
        for (int e = 0; e < HD; e++) {
            float s = 0.f;
#pragma unroll
            for (int d = 0; d < HD; d++) s += k_w[e * HD + d] * qr[d];
            qt[e] = s * 0.17677669529663687f;   /* 32^-0.5 */
        }
    }
    float acc[HD];
#pragma unroll
    for (int d = 0; d < HD; d++) acc[d] = 0.f;
    float mx = -INFINITY, ls = 0.f;
    for (int mkey = 0; mkey < NPRI; mkey++) {
        const float* kr = &kx_s[mkey * HD];
        float s = 0.f;
#pragma unroll
        for (int e = 0; e < HD; e++) s += qt[e] * kr[e];
        float mn = fmaxf(mx, s);
        float corr = expf(mx - mn);
        float p = expf(s - mn);
        ls = ls * corr + p;
#pragma unroll
        for (int d = 0; d < HD; d++) acc[d] = acc[d] * corr + p * kr[d];
        mx = mn;
    }
    float inv = 1.f / ls;
#pragma unroll
    for (int d = 0; d < HD; d++)
        g_ctx[(size_t)(b * NPRI + tid) * HID + g * HD + d] = acc[d] * inv;
}

/* ------------------------- final heads + output assembly ------------------------- */
__global__ void head_k(const float* __restrict__ cls_w, const float* __restrict__ cls_b,
                       const float* __restrict__ reg_w, const float* __restrict__ reg_b,
                       const float* __restrict__ priors, float* __restrict__ out) {
    __shared__ float sc[3][HID], sr[3][HID];
    int m0 = blockIdx.x * 3;
    int tid = threadIdx.y * 76 + threadIdx.x;
    for (int i = tid; i < 3 * HID; i += 228) {
        int r = i / HID, c = i % HID;
        sc[r][c] = g_clsf[(size_t)(m0 + r) * HID + c];
        sr[r][c] = g_regf[(size_t)(m0 + r) * HID + c];
    }
    __syncthreads();
    int r = threadIdx.y, col = threadIdx.x;
    int m = m0 + r;
    float v;
    if (col < 2) {
        v = cls_b[col];
        for (int e = 0; e < HID; e++) v += sc[r][e] * cls_w[e * 2 + col];
    } else {
        int jj = col - 2;
        v = reg_b[jj] + priors[(size_t)m * PRI_DIM + col];
        for (int e = 0; e < HID; e++) v += sr[r][e] * reg_w[e * 74 + jj];
    }
    out[(size_t)m * OUT_COLS + col] = v;
}

/* ------------------------- host driver ------------------------- */
extern "C" void kernel_launch(void* const* d_in, const int* in_sizes, int n_in,
                              void* d_out, int out_size) {
    const float* feat0   = (const float*)d_in[0];
    const float* feat1   = (const float*)d_in[1];
    const float* feat2   = (const float*)d_in[2];
    const float* priors  = (const float*)d_in[3];
    const float* z_emb   = (const float*)d_in[4];
    const float* gather_w= (const float*)d_in[5];
    const float* gather_b= (const float*)d_in[6];
    const float* q_w     = (const float*)d_in[7];
    const float* k_w     = (const float*)d_in[8];
    const float* ch_w1   = (const float*)d_in[9];
    const float* ch_b1   = (const float*)d_in[10];
    const float* ch_w2   = (const float*)d_in[11];
    const float* ch_b2   = (const float*)d_in[12];
    const float* reg_m_w = (const float*)d_in[13];
    const float* reg_m_b = (const float*)d_in[14];
    const float* cls_m_w = (const float*)d_in[15];
    const float* cls_m_b = (const float*)d_in[16];
    const float* reg_w   = (const float*)d_in[17];
    const float* reg_b   = (const float*)d_in[18];
    const float* cls_w   = (const float*)d_in[19];
    const float* cls_b   = (const float*)d_in[20];
    float* out = (float*)d_out;

    float *p_nhwc0, *p_nhwc1, *p_nhwc2, *p_feature, *p_feat, *p_q, *p_ctx, *p_h,
          *p_fc, *p_clsf, *p_regf;
    cudaGetSymbolAddress((void**)&p_nhwc0, g_nhwc0);
    cudaGetSymbolAddress((void**)&p_nhwc1, g_nhwc1);
    cudaGetSymbolAddress((void**)&p_nhwc2, g_nhwc2);
    cudaGetSymbolAddress((void**)&p_feature, g_feature);
    cudaGetSymbolAddress((void**)&p_feat, g_feat);
    cudaGetSymbolAddress((void**)&p_q, g_q);
    cudaGetSymbolAddress((void**)&p_ctx, g_ctx);
    cudaGetSymbolAddress((void**)&p_h, g_h);
    cudaGetSymbolAddress((void**)&p_fc, g_fc);
    cudaGetSymbolAddress((void**)&p_clsf, g_clsf);
    cudaGetSymbolAddress((void**)&p_regf, g_regf);

    dim3 tb(32, 8);
    transpose_k<<<dim3(8,   2, BATCH), tb>>>(feat0, p_nhwc0, 64, 250);
    transpose_k<<<dim3(32,  2, BATCH), tb>>>(feat1, p_nhwc1, 64, 1000);
    transpose_k<<<dim3(125, 2, BATCH), tb>>>(feat2, p_nhwc2, 64, 4000);

    meta_k<<<(MS + 255) / 256, 256>>>(priors, z_emb);
    gather_k<<<MS / 8, dim3(32, 8)>>>();

    /* gather_fc: single launch, gridDim.y = group */
    gemm_k<64, 32, 32, true, true, false, false, true, false><<<dim3(M_ROWS / 64, GRP), 128>>>(
        p_feature, gather_w, gather_b, nullptr, p_feat,
        M_ROWS, 32, 384, SP * CF, 384, HID);

    /* q = feat @ q_w */
    gemm_k<64, 64, 32, false, false, false, false, false, false><<<dim3(M_ROWS / 64, 3), 256>>>(
        p_feat, q_w, nullptr, nullptr, p_q, M_ROWS, HID, HID, HID, HID, HID);

    attn_k<<<dim3(GRP, BATCH), 192>>>(k_w);

    /* channel MLP: h = relu(ctx @ ch_w1 + b1); fc = feat + h @ ch_w2 + b2 */
    gemm_k<64, 64, 32, false, true, true, false, false, false><<<dim3(M_ROWS / 64, 6), 256>>>(
        p_ctx, ch_w1, ch_b1, nullptr, p_h, M_ROWS, 2 * HID, HID, HID, 2 * HID, 2 * HID);
    gemm_k<64, 64, 32, false, true, false, true, false, false><<<dim3(M_ROWS / 64, 3), 256>>>(
        p_h, ch_w2, ch_b2, p_feat, p_fc, M_ROWS, HID, 2 * HID, 2 * HID, HID, HID);

    /* heads: cls_m and reg_m merged into one launch (DUAL) */
    gemm_k<64, 64, 32, false, true, true, false, false, true><<<dim3(M_ROWS / 64, 6), 256>>>(
        p_fc, cls_m_w, cls_m_b, nullptr, p_clsf, M_ROWS, HID, HID, HID, HID, HID,
        reg_m_w, reg_m_b, p_regf);

    head_k<<<M_ROWS / 3, dim3(76, 3)>>>(cls_w, cls_b, reg_w, reg_b, priors, out);
}

// round 7
// speedup vs baseline: 1.2581x; 1.1181x over previous
#include <cuda_runtime.h>
#include <math.h>
#include <stdint.h>

#define BATCH 64
#define NPRI 192
#define SP 36
#define CF 64
#define HID 192
#define GRP 6
#define HD 32
#define M_ROWS (BATCH*NPRI)   /* 12288 */
#define PRI_DIM 76
#define OUT_COLS 76
#define MS (M_ROWS*SP)        /* 442368 (m,s) pairs */

/* ------------------------- scratch (static device) ------------------------- */
__device__ float g_nhwc0[BATCH*10*25*CF];
__device__ float g_nhwc1[BATCH*20*50*CF];
__device__ float g_nhwc2[BATCH*40*100*CF];
__device__ int   g_meta[24*(size_t)MS];             /* SoA: [field][t], field = lvl*8+q */
__device__ float g_feature[(size_t)MS*CF];          /* (m, s, c) 113MB */
__device__ float g_feat[M_ROWS*HID];
__device__ float g_q[M_ROWS*HID];
__device__ float g_ctx[M_ROWS*HID];
__device__ float g_h[M_ROWS*2*HID];
__device__ float g_fc[M_ROWS*HID];
__device__ float g_clsf[M_ROWS*HID];
__device__ float g_regf[M_ROWS*HID];

/* ------------------------- NCHW -> NHWC transpose ------------------------- */
__global__ void transpose_k(const float* __restrict__ in, float* __restrict__ out,
                            int C, int HW) {
    __shared__ float tile[32][33];
    int b  = blockIdx.z;
    int p0 = blockIdx.x * 32;
    int c0 = blockIdx.y * 32;
    const float* inb = in  + (size_t)b * C * HW;
    float*       outb = out + (size_t)b * C * HW;
    for (int i = threadIdx.y; i < 32; i += 8) {
        int c = c0 + i, p = p0 + threadIdx.x;
        tile[i][threadIdx.x] = (p < HW) ? inb[(size_t)c * HW + p] : 0.f;
    }
    __syncthreads();
    for (int i = threadIdx.y; i < 32; i += 8) {
        int p = p0 + i, c = c0 + threadIdx.x;
        if (p < HW) outb[(size_t)p * C + c] = tile[threadIdx.x][i];
    }
}

/* ------------------------- sampling metadata: one thread per (m,s), SoA out -------- */
__global__ void meta_k(const float* __restrict__ priors, const float* __restrict__ z_emb) {
    int t = blockIdx.x * 256 + threadIdx.x;
    if (t >= MS) return;
    int m = t / SP, s = t % SP;
    int j = 35 - s;
    int idxj = (71 * j) / 35;                     /* = SAMPLE_X_IDX[35-s] */
    float px = priors[(size_t)m * PRI_DIM + 4 + idxj];
    float py = 1.0f - (float)idxj / 71.0f;
    float e = z_emb[s];
    float w0 = expf(-e * e * 0.5f);
    float w1 = expf(-(e - 1.f) * (e - 1.f) * 0.5f);
    float w2 = expf(-(e - 2.f) * (e - 2.f) * 0.5f);
    float inv = 1.f / (w0 + w1 + w2);
    float zw[3] = {w0 * inv, w1 * inv, w2 * inv};
    const int Hs[3] = {10, 20, 40}, Ws[3] = {25, 50, 100};
#pragma unroll
    for (int lvl = 0; lvl < 3; lvl++) {
        int W = Ws[lvl], H = Hs[lvl];
        float x = px * (float)(W - 1);            /* (gx+1)*0.5*(W-1), gx=px*2-1 */
        float y = py * (float)(H - 1);
        float x0f = floorf(x), y0f = floorf(y);
        float wx = x - x0f, wy = y - y0f;
        int x0 = (int)x0f, y0 = (int)y0f;
        bool xv0 = (x0 >= 0) && (x0 < W);
        bool xv1 = (x0 + 1 >= 0) && (x0 + 1 < W);
        bool yv0 = (y0 >= 0) && (y0 < H);
        bool yv1 = (y0 + 1 >= 0) && (y0 + 1 < H);
        int xc0 = min(max(x0, 0), W - 1);
        int xc1 = min(max(x0 + 1, 0), W - 1);
        int yc0 = min(max(y0, 0), H - 1);
        int yc1 = min(max(y0 + 1, 0), H - 1);
        float zl = zw[lvl];
        g_meta[(lvl * 8 + 0) * (size_t)MS + t] = (yc0 * W + xc0) * CF;
        g_meta[(lvl * 8 + 1) * (size_t)MS + t] = (yc0 * W + xc1) * CF;
        g_meta[(lvl * 8 + 2) * (size_t)MS + t] = (yc1 * W + xc0) * CF;
        g_meta[(lvl * 8 + 3) * (size_t)MS + t] = (yc1 * W + xc1) * CF;
        g_meta[(lvl * 8 + 4) * (size_t)MS + t] = __float_as_int((1.f - wx) * (1.f - wy) * zl * (float)(xv0 && yv0));
        g_meta[(lvl * 8 + 5) * (size_t)MS + t] = __float_as_int(wx * (1.f - wy) * zl * (float)(xv1 && yv0));
        g_meta[(lvl * 8 + 6) * (size_t)MS + t] = __float_as_int((1.f - wx) * wy * zl * (float)(xv0 && yv1));
        g_meta[(lvl * 8 + 7) * (size_t)MS + t] = __float_as_int(wx * wy * zl * (float)(xv1 && yv1));
    }
}

/* ------------------------- weighted gather: one warp per (m,s), lane = channel pair ---- */
__global__ __launch_bounds__(256) void gather_k() {
    int w = blockIdx.x * 8 + threadIdx.y;         /* (m,s) index */
    int lane = threadIdx.x;
    int m = w / SP;
    int b = m / NPRI;
    const float* base0 = g_nhwc0 + (size_t)b * 10 * 25 * CF + 2 * lane;
    const float* base1 = g_nhwc1 + (size_t)b * 20 * 50 * CF + 2 * lane;
    const float* base2 = g_nhwc2 + (size_t)b * 40 * 100 * CF + 2 * lane;
    float ax = 0.f, ay = 0.f;
#pragma unroll
    for (int lvl = 0; lvl < 3; lvl++) {
        const float* fb = (lvl == 0) ? base0 : (lvl == 1) ? base1 : base2;
        int i0 = g_meta[(lvl * 8 + 0) * (size_t)MS + w];
        int i1 = g_meta[(lvl * 8 + 1) * (size_t)MS + w];
        int i2 = g_meta[(lvl * 8 + 2) * (size_t)MS + w];
        int i3 = g_meta[(lvl * 8 + 3) * (size_t)MS + w];
        float w0 = __int_as_float(g_meta[(lvl * 8 + 4) * (size_t)MS + w]);
        float w1 = __int_as_float(g_meta[(lvl * 8 + 5) * (size_t)MS + w]);
        float w2 = __int_as_float(g_meta[(lvl * 8 + 6) * (size_t)MS + w]);
        float w3 = __int_as_float(g_meta[(lvl * 8 + 7) * (size_t)MS + w]);
        float2 v0 = *(const float2*)(fb + i0);
        float2 v1 = *(const float2*)(fb + i1);
        float2 v2 = *(const float2*)(fb + i2);
        float2 v3 = *(const float2*)(fb + i3);
        ax += w0 * v0.x + w1 * v1.x + w2 * v2.x + w3 * v3.x;
        ay += w0 * v0.y + w1 * v1.y + w2 * v2.y + w3 * v3.y;
    }
    float2 r; r.x = ax; r.y = ay;
    *(float2*)(g_feature + (size_t)w * CF + 2 * lane) = r;
}

/* ------------------------- gather_fc GEMM (TRANSB, grouped) ------------------------- */
/* C[M,32] = A[M,384] @ Wg^T + bias, per group g = blockIdx.y. */
__global__ __launch_bounds__(128) void gemmg_k(const float* __restrict__ A,
                                               const float* __restrict__ B,
                                               const float* __restrict__ bias,
                                               float* __restrict__ C) {
    constexpr int BM = 64, BN = 32, BK = 32, K = 384;
    __shared__ float As[BK][BM];
    __shared__ float Bs[BK][BN];
    const int tid = threadIdx.x;
    const int tn = tid % 8;
    const int tm = tid / 8;
    const int row0 = blockIdx.x * BM;
    const int g = blockIdx.y;
    A    += (size_t)g * K;
    B    += (size_t)g * BN * K;
    bias += g * BN;
    C    += g * BN;
    float acc[4][4];
#pragma unroll
    for (int i = 0; i < 4; i++)
#pragma unroll
        for (int jj = 0; jj < 4; jj++) acc[i][jj] = 0.f;

    for (int k0 = 0; k0 < K; k0 += BK) {
        for (int i = tid; i < BM * (BK / 4); i += 128) {
            int r = i / (BK / 4), c4 = i % (BK / 4);
            float4 v = *(const float4*)(A + (size_t)(row0 + r) * (SP * CF) + k0 + c4 * 4);
            As[c4 * 4 + 0][r] = v.x; As[c4 * 4 + 1][r] = v.y;
            As[c4 * 4 + 2][r] = v.z; As[c4 * 4 + 3][r] = v.w;
        }
        for (int i = tid; i < BN * (BK / 4); i += 128) {
            int nn = i / (BK / 4), c4 = i % (BK / 4);
            float4 v = *(const float4*)(B + (size_t)nn * K + k0 + c4 * 4);
            Bs[c4 * 4 + 0][nn] = v.x; Bs[c4 * 4 + 1][nn] = v.y;
            Bs[c4 * 4 + 2][nn] = v.z; Bs[c4 * 4 + 3][nn] = v.w;
        }
        __syncthreads();
#pragma unroll
        for (int k = 0; k < BK; k++) {
            float4 a4 = *(const float4*)&As[k][tm * 4];
            float4 b4 = *(const float4*)&Bs[k][tn * 4];
            float a[4] = {a4.x, a4.y, a4.z, a4.w};
            float bb[4] = {b4.x, b4.y, b4.z, b4.w};
#pragma unroll
            for (int i = 0; i < 4; i++)
#pragma unroll
                for (int jj = 0; jj < 4; jj++) acc[i][jj] += a[i] * bb[jj];
        }
        __syncthreads();
    }
#pragma unroll
    for (int i = 0; i < 4; i++) {
        int r = row0 + tm * 4 + i;
#pragma unroll
        for (int jj = 0; jj < 4; jj++) {
            int cc = tn * 4 + jj;
            C[(size_t)r * HID + cc] = acc[i][jj] + bias[cc];
        }
    }
}

/* ------------------------- main 128x64x32 GEMM, 8x4 per thread ------------------------- */
template<bool BIAS, bool RELU, bool RES, bool DUAL>
__global__ __launch_bounds__(256) void gemm8_k(const float* __restrict__ A,
                                               const float* __restrict__ B,
                                               const float* __restrict__ bias,
                                               const float* __restrict__ res,
                                               float* __restrict__ C,
                                               int K, int ldb, int ldc,
                                               const float* __restrict__ B2 = nullptr,
                                               const float* __restrict__ bias2 = nullptr,
                                               float* __restrict__ C2 = nullptr) {
    constexpr int BM = 128, BN = 64, BK = 32;
    __shared__ float As[BK][BM + 4];
    __shared__ float Bs[BK][BN];
    const int tid = threadIdx.x;
    const int tn = tid % 16;           /* 16 col-groups of 4 */
    const int tm = tid / 16;           /* 16 row-groups of 8 */
    const int row0 = blockIdx.x * BM;
    const int lda = K;                 /* A rows are K-contiguous for all call sites */
    int col0;
    if (DUAL) {
        int half = gridDim.y / 2;
        int y = blockIdx.y;
        if (y >= half) { B = B2; bias = bias2; C = C2; y -= half; }
        col0 = y * BN;
    } else {
        col0 = blockIdx.y * BN;
    }
    float acc[8][4];
#pragma unroll
    for (int i = 0; i < 8; i++)
#pragma unroll
        for (int jj = 0; jj < 4; jj++) acc[i][jj] = 0.f;

    for (int k0 = 0; k0 < K; k0 += BK) {
#pragma unroll
        for (int it = 0; it < 4; it++) {           /* A: 128 rows x 8 float4 */
            int i = tid + it * 256;
            int r = i >> 3, c4 = i & 7;
            float4 v = *(const float4*)(A + (size_t)(row0 + r) * lda + k0 + c4 * 4);
            As[c4 * 4 + 0][r] = v.x; As[c4 * 4 + 1][r] = v.y;
            As[c4 * 4 + 2][r] = v.z; As[c4 * 4 + 3][r] = v.w;
        }
#pragma unroll
        for (int it = 0; it < 2; it++) {           /* B: 32 rows x 16 float4 */
            int i = tid + it * 256;
            int r = i >> 4, c4 = i & 15;
            *(float4*)&Bs[r][c4 * 4] =
                *(const float4*)(B + (size_t)(k0 + r) * ldb + col0 + c4 * 4);
        }
        __syncthreads();
#pragma unroll
        for (int k = 0; k < BK; k++) {
            float4 a0 = *(const float4*)&As[k][tm * 8];
            float4 a1 = *(const float4*)&As[k][tm * 8 + 4];
            float4 b4 = *(const float4*)&Bs[k][tn * 4];
            float a[8] = {a0.x, a0.y, a0.z, a0.w, a1.x, a1.y, a1.z, a1.w};
            float bb[4] = {b4.x, b4.y, b4.z, b4.w};
#pragma unroll
            for (int i = 0; i < 8; i++)
#pragma unroll
                for (int jj = 0; jj < 4; jj++) acc[i][jj] += a[i] * bb[jj];
        }
        __syncthreads();
    }
    float4 bv = {0.f, 0.f, 0.f, 0.f};
    if (BIAS) bv = *(const float4*)(bias + col0 + tn * 4);
#pragma unroll
    for (int i = 0; i < 8; i++) {
        int r = row0 + tm * 8 + i;
        float4 v;
        v.x = acc[i][0] + bv.x; v.y = acc[i][1] + bv.y;
        v.z = acc[i][2] + bv.z; v.w = acc[i][3] + bv.w;
        if (RELU) {
            v.x = fmaxf(v.x, 0.f); v.y = fmaxf(v.y, 0.f);
            v.z = fmaxf(v.z, 0.f); v.w = fmaxf(v.w, 0.f);
        }
        if (RES) {
            float4 rv = *(const float4*)(res + (size_t)r * ldc + col0 + tn * 4);
            v.x += rv.x; v.y += rv.y; v.z += rv.z; v.w += rv.w;
        }
        *(float4*)(C + (size_t)r * ldc + col0 + tn * 4) = v;
    }
}

/* ------------------------- per-(b,g) attention, flash-style -------------------------
 * s = scale * q . (kx @ k_w)  ==  (scale * k_w^T q) . kx  -> only kx tile in smem. */
__global__ __launch_bounds__(192) void attn_k(const float* __restrict__ k_w) {
    int g = blockIdx.x, b = blockIdx.y;
    __shared__ float kx_s[NPRI * HD];     /* 24 KB */
    int tid = threadIdx.x;                /* 0..191 = query index */
    for (int i = tid; i < NPRI * HD; i += 192) {
        int n = i / HD, d = i % HD;
        kx_s[i] = g_feat[(size_t)(b * NPRI + n) * HID + g * HD + d];
    }
    __syncthreads();

    float qt[HD];
    {
        float qr[HD];
#pragma unroll
        for (int d = 0; d < HD; d++)
            qr[d] = g_q[(size_t)(b * NPRI + tid) * HID + g * HD + d];
#pragma unroll
        for (int e = 0; e < HD; e++) {
            float s = 0.f;
#pragma unroll
            for (int d = 0; d < HD; d++) s += k_w[e * HD + d] * qr[d];
            qt[e] = s * 0.17677669529663687f;   /* 32^-0.5 */
        }
    }
    float acc[HD];
#pragma unroll
    for (int d = 0; d < HD; d++) acc[d] = 0.f;
    float mx = -INFINITY, ls = 0.f;
    for (int mkey = 0; mkey < NPRI; mkey++) {
        const float* kr = &kx_s[mkey * HD];
        float s = 0.f;
#pragma unroll
        for (int e = 0; e < HD; e++) s += qt[e] * kr[e];
        float mn = fmaxf(mx, s);
        float corr = expf(mx - mn);
        float p = expf(s - mn);
        ls = ls * corr + p;
#pragma unroll
        for (int d = 0; d < HD; d++) acc[d] = acc[d] * corr + p * kr[d];
        mx = mn;
    }
    float inv = 1.f / ls;
#pragma unroll
    for (int d = 0; d < HD; d++)
        g_ctx[(size_t)(b * NPRI + tid) * HID + g * HD + d] = acc[d] * inv;
}

/* ------------------------- final heads + output assembly ------------------------- */
__global__ void head_k(const float* __restrict__ cls_w, const float* __restrict__ cls_b,
                       const float* __restrict__ reg_w, const float* __restrict__ reg_b,
                       const float* __restrict__ priors, float* __restrict__ out) {
    __shared__ float sc[3][HID], sr[3][HID];
    int m0 = blockIdx.x * 3;
    int tid = threadIdx.y * 76 + threadIdx.x;
    for (int i = tid; i < 3 * HID; i += 228) {
        int r = i / HID, c = i % HID;
        sc[r][c] = g_clsf[(size_t)(m0 + r) * HID + c];
        sr[r][c] = g_regf[(size_t)(m0 + r) * HID + c];
    }
    __syncthreads();
    int r = threadIdx.y, col = threadIdx.x;
    int m = m0 + r;
    float v;
    if (col < 2) {
        v = cls_b[col];
        for (int e = 0; e < HID; e++) v += sc[r][e] * cls_w[e * 2 + col];
    } else {
        int jj = col - 2;
        v = reg_b[jj] + priors[(size_t)m * PRI_DIM + col];
        for (int e = 0; e < HID; e++) v += sr[r][e] * reg_w[e * 74 + jj];
    }
    out[(size_t)m * OUT_COLS + col] = v;
}

/* ------------------------- host driver ------------------------- */
extern "C" void kernel_launch(void* const* d_in, const int* in_sizes, int n_in,
                              void* d_out, int out_size) {
    const float* feat0   = (const float*)d_in[0];
    const float* feat1   = (const float*)d_in[1];
    const float* feat2   = (const float*)d_in[2];
    const float* priors  = (const float*)d_in[3];
    const float* z_emb   = (const float*)d_in[4];
    const float* gather_w= (const float*)d_in[5];
    const float* gather_b= (const float*)d_in[6];
    const float* q_w     = (const float*)d_in[7];
    const float* k_w     = (const float*)d_in[8];
    const float* ch_w1   = (const float*)d_in[9];
    const float* ch_b1   = (const float*)d_in[10];
    const float* ch_w2   = (const float*)d_in[11];
    const float* ch_b2   = (const float*)d_in[12];
    const float* reg_m_w = (const float*)d_in[13];
    const float* reg_m_b = (const float*)d_in[14];
    const float* cls_m_w = (const float*)d_in[15];
    const float* cls_m_b = (const float*)d_in[16];
    const float* reg_w   = (const float*)d_in[17];
    const float* reg_b   = (const float*)d_in[18];
    const float* cls_w   = (const float*)d_in[19];
    const float* cls_b   = (const float*)d_in[20];
    float* out = (float*)d_out;

    float *p_nhwc0, *p_nhwc1, *p_nhwc2, *p_feature, *p_feat, *p_q, *p_ctx, *p_h,
          *p_fc, *p_clsf, *p_regf;
    cudaGetSymbolAddress((void**)&p_nhwc0, g_nhwc0);
    cudaGetSymbolAddress((void**)&p_nhwc1, g_nhwc1);
    cudaGetSymbolAddress((void**)&p_nhwc2, g_nhwc2);
    cudaGetSymbolAddress((void**)&p_feature, g_feature);
    cudaGetSymbolAddress((void**)&p_feat, g_feat);
    cudaGetSymbolAddress((void**)&p_q, g_q);
    cudaGetSymbolAddress((void**)&p_ctx, g_ctx);
    cudaGetSymbolAddress((void**)&p_h, g_h);
    cudaGetSymbolAddress((void**)&p_fc, g_fc);
    cudaGetSymbolAddress((void**)&p_clsf, g_clsf);
    cudaGetSymbolAddress((void**)&p_regf, g_regf);

    dim3 tb(32, 8);
    transpose_k<<<dim3(8,   2, BATCH), tb>>>(feat0, p_nhwc0, 64, 250);
    transpose_k<<<dim3(32,  2, BATCH), tb>>>(feat1, p_nhwc1, 64, 1000);
    transpose_k<<<dim3(125, 2, BATCH), tb>>>(feat2, p_nhwc2, 64, 4000);

    meta_k<<<(MS + 255) / 256, 256>>>(priors, z_emb);
    gather_k<<<MS / 8, dim3(32, 8)>>>();

    /* gather_fc: gridDim.y = group */
    gemmg_k<<<dim3(M_ROWS / 64, GRP), 128>>>(p_feature, gather_w, gather_b, p_feat);

    /* q = feat @ q_w */
    gemm8_k<false, false, false, false><<<dim3(M_ROWS / 128, 3), 256>>>(
        p_feat, q_w, nullptr, nullptr, p_q, HID, HID, HID);

    attn_k<<<dim3(GRP, BATCH), 192>>>(k_w);

    /* channel MLP: h = relu(ctx @ ch_w1 + b1); fc = feat + h @ ch_w2 + b2 */
    gemm8_k<true, true, false, false><<<dim3(M_ROWS / 128, 6), 256>>>(
        p_ctx, ch_w1, ch_b1, nullptr, p_h, HID, 2 * HID, 2 * HID);
    gemm8_k<true, false, true, false><<<dim3(M_ROWS / 128, 3), 256>>>(
        p_h, ch_w2, ch_b2, p_feat, p_fc, 2 * HID, HID, HID);

    /* heads: cls_m and reg_m merged into one launch (DUAL) */
    gemm8_k<true, true, false, true><<<dim3(M_ROWS / 128, 6), 256>>>(
        p_fc, cls_m_w, cls_m_b, nullptr, p_clsf, HID, HID, HID,
        reg_m_w, reg_m_b, p_regf);

    head_k<<<M_ROWS / 3, dim3(76, 3)>>>(cls_w, cls_b, reg_w, reg_b, priors, out);
}

// round 8
// speedup vs baseline: 1.4214x; 1.1298x over previous
#include <cuda_runtime.h>
#include <math.h>
#include <stdint.h>

#define BATCH 64
#define NPRI 192
#define SP 36
#define CF 64
#define HID 192
#define GRP 6
#define HD 32
#define M_ROWS (BATCH*NPRI)   /* 12288 */
#define PRI_DIM 76
#define OUT_COLS 76
#define MS (M_ROWS*SP)        /* 442368 (m,s) pairs */

/* ------------------------- scratch (static device) ------------------------- */
__device__ float g_nhwc0[BATCH*10*25*CF];
__device__ float g_nhwc1[BATCH*20*50*CF];
__device__ float g_nhwc2[BATCH*40*100*CF];
__device__ int   g_meta[24*(size_t)MS];             /* SoA: [field][t] */
__device__ float g_feature[(size_t)MS*CF];          /* (m, s, c) 113MB */
__device__ float g_feat[M_ROWS*HID];
__device__ float g_q[M_ROWS*HID];
__device__ float g_ctx[M_ROWS*HID];
__device__ float g_h[M_ROWS*2*HID];
__device__ float g_fc[M_ROWS*HID];
__device__ float g_clsf[M_ROWS*HID];
__device__ float g_regf[M_ROWS*HID];

/* ------------------------- NCHW -> NHWC transpose ------------------------- */
__global__ void transpose_k(const float* __restrict__ in, float* __restrict__ out,
                            int C, int HW) {
    __shared__ float tile[32][33];
    int b  = blockIdx.z;
    int p0 = blockIdx.x * 32;
    int c0 = blockIdx.y * 32;
    const float* inb = in  + (size_t)b * C * HW;
    float*       outb = out + (size_t)b * C * HW;
    for (int i = threadIdx.y; i < 32; i += 8) {
        int c = c0 + i, p = p0 + threadIdx.x;
        tile[i][threadIdx.x] = (p < HW) ? inb[(size_t)c * HW + p] : 0.f;
    }
    __syncthreads();
    for (int i = threadIdx.y; i < 32; i += 8) {
        int p = p0 + i, c = c0 + threadIdx.x;
        if (p < HW) outb[(size_t)p * C + c] = tile[threadIdx.x][i];
    }
}

/* ------------------------- sampling metadata: one thread per (m,s), SoA out -------- */
__global__ void meta_k(const float* __restrict__ priors, const float* __restrict__ z_emb) {
    int t = blockIdx.x * 256 + threadIdx.x;
    if (t >= MS) return;
    int m = t / SP, s = t % SP;
    int j = 35 - s;
    int idxj = (71 * j) / 35;                     /* = SAMPLE_X_IDX[35-s] */
    float px = priors[(size_t)m * PRI_DIM + 4 + idxj];
    float py = 1.0f - (float)idxj / 71.0f;
    float e = z_emb[s];
    float w0 = expf(-e * e * 0.5f);
    float w1 = expf(-(e - 1.f) * (e - 1.f) * 0.5f);
    float w2 = expf(-(e - 2.f) * (e - 2.f) * 0.5f);
    float inv = 1.f / (w0 + w1 + w2);
    float zw[3] = {w0 * inv, w1 * inv, w2 * inv};
    const int Hs[3] = {10, 20, 40}, Ws[3] = {25, 50, 100};
#pragma unroll
    for (int lvl = 0; lvl < 3; lvl++) {
        int W = Ws[lvl], H = Hs[lvl];
        float x = px * (float)(W - 1);
        float y = py * (float)(H - 1);
        float x0f = floorf(x), y0f = floorf(y);
        float wx = x - x0f, wy = y - y0f;
        int x0 = (int)x0f, y0 = (int)y0f;
        bool xv0 = (x0 >= 0) && (x0 < W);
        bool xv1 = (x0 + 1 >= 0) && (x0 + 1 < W);
        bool yv0 = (y0 >= 0) && (y0 < H);
        bool yv1 = (y0 + 1 >= 0) && (y0 + 1 < H);
        int xc0 = min(max(x0, 0), W - 1);
        int xc1 = min(max(x0 + 1, 0), W - 1);
        int yc0 = min(max(y0, 0), H - 1);
        int yc1 = min(max(y0 + 1, 0), H - 1);
        float zl = zw[lvl];
        g_meta[(lvl * 8 + 0) * (size_t)MS + t] = (yc0 * W + xc0) * CF;
        g_meta[(lvl * 8 + 1) * (size_t)MS + t] = (yc0 * W + xc1) * CF;
        g_meta[(lvl * 8 + 2) * (size_t)MS + t] = (yc1 * W + xc0) * CF;
        g_meta[(lvl * 8 + 3) * (size_t)MS + t] = (yc1 * W + xc1) * CF;
        g_meta[(lvl * 8 + 4) * (size_t)MS + t] = __float_as_int((1.f - wx) * (1.f - wy) * zl * (float)(xv0 && yv0));
        g_meta[(lvl * 8 + 5) * (size_t)MS + t] = __float_as_int(wx * (1.f - wy) * zl * (float)(xv1 && yv0));
        g_meta[(lvl * 8 + 6) * (size_t)MS + t] = __float_as_int((1.f - wx) * wy * zl * (float)(xv0 && yv1));
        g_meta[(lvl * 8 + 7) * (size_t)MS + t] = __float_as_int(wx * wy * zl * (float)(xv1 && yv1));
    }
}

/* ------------------------- weighted gather: one warp per (m,s) ------------------------- */
__global__ __launch_bounds__(256) void gather_k() {
    int w = blockIdx.x * 8 + threadIdx.y;
    int lane = threadIdx.x;
    int m = w / SP;
    int b = m / NPRI;
    const float* base0 = g_nhwc0 + (size_t)b * 10 * 25 * CF + 2 * lane;
    const float* base1 = g_nhwc1 + (size_t)b * 20 * 50 * CF + 2 * lane;
    const float* base2 = g_nhwc2 + (size_t)b * 40 * 100 * CF + 2 * lane;
    float ax = 0.f, ay = 0.f;
#pragma unroll
    for (int lvl = 0; lvl < 3; lvl++) {
        const float* fb = (lvl == 0) ? base0 : (lvl == 1) ? base1 : base2;
        int i0 = g_meta[(lvl * 8 + 0) * (size_t)MS + w];
        int i1 = g_meta[(lvl * 8 + 1) * (size_t)MS + w];
        int i2 = g_meta[(lvl * 8 + 2) * (size_t)MS + w];
        int i3 = g_meta[(lvl * 8 + 3) * (size_t)MS + w];
        float w0 = __int_as_float(g_meta[(lvl * 8 + 4) * (size_t)MS + w]);
        float w1 = __int_as_float(g_meta[(lvl * 8 + 5) * (size_t)MS + w]);
        float w2 = __int_as_float(g_meta[(lvl * 8 + 6) * (size_t)MS + w]);
        float w3 = __int_as_float(g_meta[(lvl * 8 + 7) * (size_t)MS + w]);
        float2 v0 = *(const float2*)(fb + i0);
        float2 v1 = *(const float2*)(fb + i1);
        float2 v2 = *(const float2*)(fb + i2);
        float2 v3 = *(const float2*)(fb + i3);
        ax += w0 * v0.x + w1 * v1.x + w2 * v2.x + w3 * v3.x;
        ay += w0 * v0.y + w1 * v1.y + w2 * v2.y + w3 * v3.y;
    }
    float2 r; r.x = ax; r.y = ay;
    *(float2*)(g_feature + (size_t)w * CF + 2 * lane) = r;
}

/* ------------------------- gather_fc GEMM (fp32 SIMT, grouped) ------------------------- */
__global__ __launch_bounds__(128) void gemmg_k(const float* __restrict__ A,
                                               const float* __restrict__ B,
                                               const float* __restrict__ bias,
                                               float* __restrict__ C) {
    constexpr int BM = 64, BN = 32, BK = 32, K = 384;
    __shared__ float As[BK][BM];
    __shared__ float Bs[BK][BN];
    const int tid = threadIdx.x;
    const int tn = tid % 8;
    const int tm = tid / 8;
    const int row0 = blockIdx.x * BM;
    const int g = blockIdx.y;
    A    += (size_t)g * K;
    B    += (size_t)g * BN * K;
    bias += g * BN;
    C    += g * BN;
    float acc[4][4];
#pragma unroll
    for (int i = 0; i < 4; i++)
#pragma unroll
        for (int jj = 0; jj < 4; jj++) acc[i][jj] = 0.f;

    for (int k0 = 0; k0 < K; k0 += BK) {
        for (int i = tid; i < BM * (BK / 4); i += 128) {
            int r = i / (BK / 4), c4 = i % (BK / 4);
            float4 v = *(const float4*)(A + (size_t)(row0 + r) * (SP * CF) + k0 + c4 * 4);
            As[c4 * 4 + 0][r] = v.x; As[c4 * 4 + 1][r] = v.y;
            As[c4 * 4 + 2][r] = v.z; As[c4 * 4 + 3][r] = v.w;
        }
        for (int i = tid; i < BN * (BK / 4); i += 128) {
            int nn = i / (BK / 4), c4 = i % (BK / 4);
            float4 v = *(const float4*)(B + (size_t)nn * K + k0 + c4 * 4);
            Bs[c4 * 4 + 0][nn] = v.x; Bs[c4 * 4 + 1][nn] = v.y;
            Bs[c4 * 4 + 2][nn] = v.z; Bs[c4 * 4 + 3][nn] = v.w;
        }
        __syncthreads();
#pragma unroll
        for (int k = 0; k < BK; k++) {
            float4 a4 = *(const float4*)&As[k][tm * 4];
            float4 b4 = *(const float4*)&Bs[k][tn * 4];
            float a[4] = {a4.x, a4.y, a4.z, a4.w};
            float bb[4] = {b4.x, b4.y, b4.z, b4.w};
#pragma unroll
            for (int i = 0; i < 4; i++)
#pragma unroll
                for (int jj = 0; jj < 4; jj++) acc[i][jj] += a[i] * bb[jj];
        }
        __syncthreads();
    }
#pragma unroll
    for (int i = 0; i < 4; i++) {
        int r = row0 + tm * 4 + i;
#pragma unroll
        for (int jj = 0; jj < 4; jj++) {
            int cc = tn * 4 + jj;
            C[(size_t)r * HID + cc] = acc[i][jj] + bias[cc];
        }
    }
}

/* ------------------------- tf32 tensor-core GEMM 128x64x32 ------------------------- */
__device__ __forceinline__ uint32_t f2tf(float x) {
    uint32_t u;
    asm("cvt.rna.tf32.f32 %0, %1;" : "=r"(u) : "f"(x));
    return u;
}
__device__ __forceinline__ void mma_tf32(float* c, const uint32_t* a, const uint32_t* b) {
    asm volatile(
        "mma.sync.aligned.m16n8k8.row.col.f32.tf32.tf32.f32 "
        "{%0,%1,%2,%3}, {%4,%5,%6,%7}, {%8,%9}, {%0,%1,%2,%3};"
        : "+f"(c[0]), "+f"(c[1]), "+f"(c[2]), "+f"(c[3])
        : "r"(a[0]), "r"(a[1]), "r"(a[2]), "r"(a[3]), "r"(b[0]), "r"(b[1]));
}

template<bool BIAS, bool RELU, bool RES, bool DUAL>
__global__ __launch_bounds__(256) void gemmt_k(const float* __restrict__ A,
                                               const float* __restrict__ B,
                                               const float* __restrict__ bias,
                                               const float* __restrict__ res,
                                               float* __restrict__ C,
                                               int K, int ldb, int ldc,
                                               const float* __restrict__ B2 = nullptr,
                                               const float* __restrict__ bias2 = nullptr,
                                               float* __restrict__ C2 = nullptr) {
    constexpr int BM = 128, BN = 64, BK = 32;
    __shared__ uint32_t As[BM][36];   /* m-major, 32 k + 4 pad: CF frag LDS */
    __shared__ uint32_t Bs[BK][72];   /* k-major, 64 n + 8 pad: CF frag LDS */
    const int tid = threadIdx.x;
    const int lane = tid & 31;
    const int warp = tid >> 5;
    const int wm = warp >> 1;          /* 0..3 -> m offset wm*32 */
    const int wn = warp & 1;           /* 0..1 -> n offset wn*32 */
    const int row0 = blockIdx.x * BM;
    const int lda = K;
    int col0;
    if (DUAL) {
        int half = gridDim.y / 2;
        int y = blockIdx.y;
        if (y >= half) { B = B2; bias = bias2; C = C2; y -= half; }
        col0 = y * BN;
    } else {
        col0 = blockIdx.y * BN;
    }

    float c[2][4][4];
#pragma unroll
    for (int mf = 0; mf < 2; mf++)
#pragma unroll
        for (int nf = 0; nf < 4; nf++)
#pragma unroll
            for (int i = 0; i < 4; i++) c[mf][nf][i] = 0.f;

    for (int k0 = 0; k0 < K; k0 += BK) {
#pragma unroll
        for (int it = 0; it < 4; it++) {           /* A: 128 rows x 8 float4 */
            int i = tid + it * 256;
            int r = i >> 3, c4 = i & 7;
            float4 v = *(const float4*)(A + (size_t)(row0 + r) * lda + k0 + c4 * 4);
            uint4 u;
            u.x = f2tf(v.x); u.y = f2tf(v.y); u.z = f2tf(v.z); u.w = f2tf(v.w);
            *(uint4*)&As[r][c4 * 4] = u;
        }
#pragma unroll
        for (int it = 0; it < 2; it++) {           /* B: 32 k-rows x 16 float4 */
            int i = tid + it * 256;
            int r = i >> 4, c4 = i & 15;
            float4 v = *(const float4*)(B + (size_t)(k0 + r) * ldb + col0 + c4 * 4);
            uint4 u;
            u.x = f2tf(v.x); u.y = f2tf(v.y); u.z = f2tf(v.z); u.w = f2tf(v.w);
            *(uint4*)&Bs[r][c4 * 4] = u;
        }
        __syncthreads();
#pragma unroll
        for (int ks = 0; ks < 4; ks++) {
            int k8 = ks * 8;
            int kk = k8 + (lane & 3);
            uint32_t a[2][4], b[4][2];
#pragma unroll
            for (int mf = 0; mf < 2; mf++) {
                int mr = wm * 32 + mf * 16 + (lane >> 2);
                a[mf][0] = As[mr][kk];
                a[mf][1] = As[mr + 8][kk];
                a[mf][2] = As[mr][kk + 4];
                a[mf][3] = As[mr + 8][kk + 4];
            }
#pragma unroll
            for (int nf = 0; nf < 4; nf++) {
                int nc = wn * 32 + nf * 8 + (lane >> 2);
                b[nf][0] = Bs[kk][nc];
                b[nf][1] = Bs[kk + 4][nc];
            }
#pragma unroll
            for (int mf = 0; mf < 2; mf++)
#pragma unroll
                for (int nf = 0; nf < 4; nf++)
                    mma_tf32(c[mf][nf], a[mf], b[nf]);
        }
        __syncthreads();
    }

    /* epilogue */
#pragma unroll
    for (int mf = 0; mf < 2; mf++) {
        int r = row0 + wm * 32 + mf * 16 + (lane >> 2);
#pragma unroll
        for (int nf = 0; nf < 4; nf++) {
            int ce = col0 + wn * 32 + nf * 8 + 2 * (lane & 3);
            float bx = 0.f, by = 0.f;
            if (BIAS) { bx = bias[ce]; by = bias[ce + 1]; }
            float v0 = c[mf][nf][0] + bx, v1 = c[mf][nf][1] + by;
            float v2 = c[mf][nf][2] + bx, v3 = c[mf][nf][3] + by;
            if (RELU) {
                v0 = fmaxf(v0, 0.f); v1 = fmaxf(v1, 0.f);
                v2 = fmaxf(v2, 0.f); v3 = fmaxf(v3, 0.f);
            }
            if (RES) {
                float2 r0 = *(const float2*)(res + (size_t)r * ldc + ce);
                float2 r1 = *(const float2*)(res + (size_t)(r + 8) * ldc + ce);
                v0 += r0.x; v1 += r0.y; v2 += r1.x; v3 += r1.y;
            }
            float2 s0; s0.x = v0; s0.y = v1;
            float2 s1; s1.x = v2; s1.y = v3;
            *(float2*)(C + (size_t)r * ldc + ce) = s0;
            *(float2*)(C + (size_t)(r + 8) * ldc + ce) = s1;
        }
    }
}

/* ------------------------- per-(b,g) attention, flash-style ------------------------- */
__global__ __launch_bounds__(192) void attn_k(const float* __restrict__ k_w) {
    int g = blockIdx.x, b = blockIdx.y;
    __shared__ float kx_s[NPRI * HD];
    int tid = threadIdx.x;
    for (int i = tid; i < NPRI * HD; i += 192) {
        int n = i / HD, d = i % HD;
        kx_s[i] = g_feat[(size_t)(b * NPRI + n) * HID + g * HD + d];
    }
    __syncthreads();

    float qt[HD];
    {
        float qr[HD];
#pragma unroll
        for (int d = 0; d < HD; d++)
            qr[d] = g_q[(size_t)(b * NPRI + tid) * HID + g * HD + d];
#pragma unroll
        for (int e = 0; e < HD; e++) {
            float s = 0.f;
#pragma unroll
            for (int d = 0; d < HD; d++) s += k_w[e * HD + d] * qr[d];
            qt[e] = s * 0.17677669529663687f;
        }
    }
    float acc[HD];
#pragma unroll
    for (int d = 0; d < HD; d++) acc[d] = 0.f;
    float mx = -INFINITY, ls = 0.f;
    for (int mkey = 0; mkey < NPRI; mkey++) {
        const float* kr = &kx_s[mkey * HD];
        float s = 0.f;
#pragma unroll
        for (int e = 0; e < HD; e++) s += qt[e] * kr[e];
        float mn = fmaxf(mx, s);
        float corr = expf(mx - mn);
        float p = expf(s - mn);
        ls = ls * corr + p;
#pragma unroll
        for (int d = 0; d < HD; d++) acc[d] = acc[d] * corr + p * kr[d];
        mx = mn;
    }
    float inv = 1.f / ls;
#pragma unroll
    for (int d = 0; d < HD; d++)
        g_ctx[(size_t)(b * NPRI + tid) * HID + g * HD + d] = acc[d] * inv;
}

/* ------------------------- final heads + output assembly ------------------------- */
__global__ void head_k(const float* __restrict__ cls_w, const float* __restrict__ cls_b,
                       const float* __restrict__ reg_w, const float* __restrict__ reg_b,
                       const float* __restrict__ priors, float* __restrict__ out) {
    __shared__ float sc[3][HID], sr[3][HID];
    int m0 = blockIdx.x * 3;
    int tid = threadIdx.y * 76 + threadIdx.x;
    for (int i = tid; i < 3 * HID; i += 228) {
        int r = i / HID, c = i % HID;
        sc[r][c] = g_clsf[(size_t)(m0 + r) * HID + c];
        sr[r][c] = g_regf[(size_t)(m0 + r) * HID + c];
    }
    __syncthreads();
    int r = threadIdx.y, col = threadIdx.x;
    int m = m0 + r;
    float v;
    if (col < 2) {
        v = cls_b[col];
        for (int e = 0; e < HID; e++) v += sc[r][e] * cls_w[e * 2 + col];
    } else {
        int jj = col - 2;
        v = reg_b[jj] + priors[(size_t)m * PRI_DIM + col];
        for (int e = 0; e < HID; e++) v += sr[r][e] * reg_w[e * 74 + jj];
    }
    out[(size_t)m * OUT_COLS + col] = v;
}

/* ------------------------- host driver ------------------------- */
extern "C" void kernel_launch(void* const* d_in, const int* in_sizes, int n_in,
                              void* d_out, int out_size) {
    const float* feat0   = (const float*)d_in[0];
    const float* feat1   = (const float*)d_in[1];
    const float* feat2   = (const float*)d_in[2];
    const float* priors  = (const float*)d_in[3];
    const float* z_emb   = (const float*)d_in[4];
    const float* gather_w= (const float*)d_in[5];
    const float* gather_b= (const float*)d_in[6];
    const float* q_w     = (const float*)d_in[7];
    const float* k_w     = (const float*)d_in[8];
    const float* ch_w1   = (const float*)d_in[9];
    const float* ch_b1   = (const float*)d_in[10];
    const float* ch_w2   = (const float*)d_in[11];
    const float* ch_b2   = (const float*)d_in[12];
    const float* reg_m_w = (const float*)d_in[13];
    const float* reg_m_b = (const float*)d_in[14];
    const float* cls_m_w = (const float*)d_in[15];
    const float* cls_m_b = (const float*)d_in[16];
    const float* reg_w   = (const float*)d_in[17];
    const float* reg_b   = (const float*)d_in[18];
    const float* cls_w   = (const float*)d_in[19];
    const float* cls_b   = (const float*)d_in[20];
    float* out = (float*)d_out;

    float *p_nhwc0, *p_nhwc1, *p_nhwc2, *p_feature, *p_feat, *p_q, *p_ctx, *p_h,
          *p_fc, *p_clsf, *p_regf;
    cudaGetSymbolAddress((void**)&p_nhwc0, g_nhwc0);
    cudaGetSymbolAddress((void**)&p_nhwc1, g_nhwc1);
    cudaGetSymbolAddress((void**)&p_nhwc2, g_nhwc2);
    cudaGetSymbolAddress((void**)&p_feature, g_feature);
    cudaGetSymbolAddress((void**)&p_feat, g_feat);
    cudaGetSymbolAddress((void**)&p_q, g_q);
    cudaGetSymbolAddress((void**)&p_ctx, g_ctx);
    cudaGetSymbolAddress((void**)&p_h, g_h);
    cudaGetSymbolAddress((void**)&p_fc, g_fc);
    cudaGetSymbolAddress((void**)&p_clsf, g_clsf);
    cudaGetSymbolAddress((void**)&p_regf, g_regf);

    dim3 tb(32, 8);
    transpose_k<<<dim3(8,   2, BATCH), tb>>>(feat0, p_nhwc0, 64, 250);
    transpose_k<<<dim3(32,  2, BATCH), tb>>>(feat1, p_nhwc1, 64, 1000);
    transpose_k<<<dim3(125, 2, BATCH), tb>>>(feat2, p_nhwc2, 64, 4000);

    meta_k<<<(MS + 255) / 256, 256>>>(priors, z_emb);
    gather_k<<<MS / 8, dim3(32, 8)>>>();

    gemmg_k<<<dim3(M_ROWS / 64, GRP), 128>>>(p_feature, gather_w, gather_b, p_feat);

    /* q = feat @ q_w (tf32 TC) */
    gemmt_k<false, false, false, false><<<dim3(M_ROWS / 128, 3), 256>>>(
        p_feat, q_w, nullptr, nullptr, p_q, HID, HID, HID);

    attn_k<<<dim3(GRP, BATCH), 192>>>(k_w);

    /* channel MLP (tf32 TC) */
    gemmt_k<true, true, false, false><<<dim3(M_ROWS / 128, 6), 256>>>(
        p_ctx, ch_w1, ch_b1, nullptr, p_h, HID, 2 * HID, 2 * HID);
    gemmt_k<true, false, true, false><<<dim3(M_ROWS / 128, 3), 256>>>(
        p_h, ch_w2, ch_b2, p_feat, p_fc, 2 * HID, HID, HID);

    /* heads merged (tf32 TC, DUAL) */
    gemmt_k<true, true, false, true><<<dim3(M_ROWS / 128, 6), 256>>>(
        p_fc, cls_m_w, cls_m_b, nullptr, p_clsf, HID, HID, HID,
        reg_m_w, reg_m_b, p_regf);

    head_k<<<M_ROWS / 3, dim3(76, 3)>>>(cls_w, cls_b, reg_w, reg_b, priors, out);
}

// round 10
// speedup vs baseline: 1.7021x; 1.1975x over previous
#include <cuda_runtime.h>
#include <cuda_fp16.h>
#include <math.h>
#include <stdint.h>

#define BATCH 64
#define NPRI 192
#define SP 36
#define CF 64
#define HID 192
#define GRP 6
#define HD 32
#define M_ROWS (BATCH*NPRI)   /* 12288 */
#define PRI_DIM 76
#define OUT_COLS 76
#define MS (M_ROWS*SP)        /* 442368 (m,s) pairs */

/* ------------------------- scratch (static device) ------------------------- */
__device__ __half g_nhwc0[BATCH*10*25*CF];
__device__ __half g_nhwc1[BATCH*20*50*CF];
__device__ __half g_nhwc2[BATCH*40*100*CF];
__device__ int    g_meta[24*(size_t)MS];            /* SoA: [field][t] */
__device__ __half g_feature[(size_t)MS*CF];         /* (m, s, c) fp16, 57MB */
__device__ __half g_wg_h[GRP*32*384];               /* gather_w fp16 */
__device__ float  g_feat[M_ROWS*HID];
__device__ float  g_q[M_ROWS*HID];
__device__ float  g_ctx[M_ROWS*HID];
__device__ float  g_h[M_ROWS*2*HID];
__device__ float  g_fc[M_ROWS*HID];
__device__ float  g_clsf[M_ROWS*HID];
__device__ float  g_regf[M_ROWS*HID];

/* ------------------------- weight fp32 -> fp16 ------------------------- */
__global__ void convw_k(const float* __restrict__ w) {
    int i = blockIdx.x * 256 + threadIdx.x;
    if (i < GRP * 32 * 384) g_wg_h[i] = __float2half(w[i]);
}

/* ------------------------- NCHW -> NHWC transpose (fp16 out) ------------------------- */
__global__ void transpose_k(const float* __restrict__ in, __half* __restrict__ out,
                            int C, int HW) {
    __shared__ float tile[32][33];
    int b  = blockIdx.z;
    int p0 = blockIdx.x * 32;
    int c0 = blockIdx.y * 32;
    const float* inb = in + (size_t)b * C * HW;
    __half* outb = out + (size_t)b * C * HW;
    for (int i = threadIdx.y; i < 32; i += 8) {
        int c = c0 + i, p = p0 + threadIdx.x;
        tile[i][threadIdx.x] = (p < HW) ? inb[(size_t)c * HW + p] : 0.f;
    }
    __syncthreads();
    for (int i = threadIdx.y; i < 32; i += 8) {
        int p = p0 + i, c = c0 + threadIdx.x;
        if (p < HW) outb[(size_t)p * C + c] = __float2half(tile[threadIdx.x][i]);
    }
}

/* ------------------------- sampling metadata: one thread per (m,s), SoA out -------- */
__global__ void meta_k(const float* __restrict__ priors, const float* __restrict__ z_emb) {
    int t = blockIdx.x * 256 + threadIdx.x;
    if (t >= MS) return;
    int m = t / SP, s = t % SP;
    int j = 35 - s;
    int idxj = (71 * j) / 35;                     /* = SAMPLE_X_IDX[35-s] */
    float px = priors[(size_t)m * PRI_DIM + 4 + idxj];
    float py = 1.0f - (float)idxj / 71.0f;
    float e = z_emb[s];
    float w0 = expf(-e * e * 0.5f);
    float w1 = expf(-(e - 1.f) * (e - 1.f) * 0.5f);
    float w2 = expf(-(e - 2.f) * (e - 2.f) * 0.5f);
    float inv = 1.f / (w0 + w1 + w2);
    float zw[3] = {w0 * inv, w1 * inv, w2 * inv};
    const int Hs[3] = {10, 20, 40}, Ws[3] = {25, 50, 100};
#pragma unroll
    for (int lvl = 0; lvl < 3; lvl++) {
        int W = Ws[lvl], H = Hs[lvl];
        float x = px * (float)(W - 1);
        float y = py * (float)(H - 1);
        float x0f = floorf(x), y0f = floorf(y);
        float wx = x - x0f, wy = y - y0f;
        int x0 = (int)x0f, y0 = (int)y0f;
        bool xv0 = (x0 >= 0) && (x0 < W);
        bool xv1 = (x0 + 1 >= 0) && (x0 + 1 < W);
        bool yv0 = (y0 >= 0) && (y0 < H);
        bool yv1 = (y0 + 1 >= 0) && (y0 + 1 < H);
        int xc0 = min(max(x0, 0), W - 1);
        int xc1 = min(max(x0 + 1, 0), W - 1);
        int yc0 = min(max(y0, 0), H - 1);
        int yc1 = min(max(y0 + 1, 0), H - 1);
        float zl = zw[lvl];
        g_meta[(lvl * 8 + 0) * (size_t)MS + t] = (yc0 * W + xc0) * CF;
        g_meta[(lvl * 8 + 1) * (size_t)MS + t] = (yc0 * W + xc1) * CF;
        g_meta[(lvl * 8 + 2) * (size_t)MS + t] = (yc1 * W + xc0) * CF;
        g_meta[(lvl * 8 + 3) * (size_t)MS + t] = (yc1 * W + xc1) * CF;
        g_meta[(lvl * 8 + 4) * (size_t)MS + t] = __float_as_int((1.f - wx) * (1.f - wy) * zl * (float)(xv0 && yv0));
        g_meta[(lvl * 8 + 5) * (size_t)MS + t] = __float_as_int(wx * (1.f - wy) * zl * (float)(xv1 && yv0));
        g_meta[(lvl * 8 + 6) * (size_t)MS + t] = __float_as_int((1.f - wx) * wy * zl * (float)(xv0 && yv1));
        g_meta[(lvl * 8 + 7) * (size_t)MS + t] = __float_as_int(wx * wy * zl * (float)(xv1 && yv1));
    }
}

/* ------------------------- weighted gather: one warp per (m,s), fp16 in/out -------- */
__global__ __launch_bounds__(256) void gather_k() {
    int w = blockIdx.x * 8 + threadIdx.y;
    int lane = threadIdx.x;
    int m = w / SP;
    int b = m / NPRI;
    const __half* base0 = g_nhwc0 + (size_t)b * 10 * 25 * CF + 2 * lane;
    const __half* base1 = g_nhwc1 + (size_t)b * 20 * 50 * CF + 2 * lane;
    const __half* base2 = g_nhwc2 + (size_t)b * 40 * 100 * CF + 2 * lane;
    float ax = 0.f, ay = 0.f;
#pragma unroll
    for (int lvl = 0; lvl < 3; lvl++) {
        const __half* fb = (lvl == 0) ? base0 : (lvl == 1) ? base1 : base2;
        int i0 = g_meta[(lvl * 8 + 0) * (size_t)MS + w];
        int i1 = g_meta[(lvl * 8 + 1) * (size_t)MS + w];
        int i2 = g_meta[(lvl * 8 + 2) * (size_t)MS + w];
        int i3 = g_meta[(lvl * 8 + 3) * (size_t)MS + w];
        float w0 = __int_as_float(g_meta[(lvl * 8 + 4) * (size_t)MS + w]);
        float w1 = __int_as_float(g_meta[(lvl * 8 + 5) * (size_t)MS + w]);
        float w2 = __int_as_float(g_meta[(lvl * 8 + 6) * (size_t)MS + w]);
        float w3 = __int_as_float(g_meta[(lvl * 8 + 7) * (size_t)MS + w]);
        float2 v0 = __half22float2(*(const __half2*)(fb + i0));
        float2 v1 = __half22float2(*(const __half2*)(fb + i1));
        float2 v2 = __half22float2(*(const __half2*)(fb + i2));
        float2 v3 = __half22float2(*(const __half2*)(fb + i3));
        ax += w0 * v0.x + w1 * v1.x + w2 * v2.x + w3 * v3.x;
        ay += w0 * v0.y + w1 * v1.y + w2 * v2.y + w3 * v3.y;
    }
    *(__half2*)(g_feature + (size_t)w * CF + 2 * lane) = __floats2half2_rn(ax, ay);
}

/* ------------------------- gather_fc fp16 TC GEMM (grouped) -------------------------
 * per group g: C[M,32] = A_h[M, 384 slice of 2304] @ Wg_h^T + bias; fp32 accum. */
__device__ __forceinline__ void mma_f16(float* c, const uint32_t* a, const uint32_t* b) {
    asm volatile(
        "mma.sync.aligned.m16n8k16.row.col.f32.f16.f16.f32 "
        "{%0,%1,%2,%3}, {%4,%5,%6,%7}, {%8,%9}, {%0,%1,%2,%3};"
        : "+f"(c[0]), "+f"(c[1]), "+f"(c[2]), "+f"(c[3])
        : "r"(a[0]), "r"(a[1]), "r"(a[2]), "r"(a[3]), "r"(b[0]), "r"(b[1]));
}

__global__ __launch_bounds__(256) void gemmg_h(const float* __restrict__ bias,
                                               float* __restrict__ C) {
    constexpr int BM = 256, BK = 32, K = 384;
    __shared__ __half As[BM][40];     /* [row][k], +8 pad */
    __shared__ __half Bs[32][40];     /* [n][k],  +8 pad */
    const int tid = threadIdx.x;
    const int lane = tid & 31;
    const int warp = tid >> 5;        /* 0..7 -> m offset warp*32 */
    const int row0 = blockIdx.x * BM;
    const int g = blockIdx.y;
    const __half* A = g_feature + (size_t)g * 384;      /* row stride SP*CF=2304 */
    const __half* B = g_wg_h + (size_t)g * 32 * 384;
    bias += g * 32;
    C    += g * 32;

    float c[2][4][4];
#pragma unroll
    for (int mf = 0; mf < 2; mf++)
#pragma unroll
        for (int nf = 0; nf < 4; nf++)
#pragma unroll
            for (int i = 0; i < 4; i++) c[mf][nf][i] = 0.f;

    for (int k0 = 0; k0 < K; k0 += BK) {
#pragma unroll
        for (int it = 0; it < 4; it++) {          /* A: 256 rows x 4 16B-chunks */
            int i = tid + it * 256;
            int r = i >> 2, c4 = i & 3;
            *(uint4*)&As[r][c4 * 8] =
                *(const uint4*)(A + (size_t)(row0 + r) * (SP * CF) + k0 + c4 * 8);
        }
        if (tid < 128) {                           /* B: 32 n-rows x 4 16B-chunks */
            int n = tid >> 2, c4 = tid & 3;
            *(uint4*)&Bs[n][c4 * 8] =
                *(const uint4*)(B + (size_t)n * K + k0 + c4 * 8);
        }
        __syncthreads();
#pragma unroll
        for (int ks = 0; ks < 2; ks++) {
            int kb = ks * 16;
            int kq = kb + 2 * (lane & 3);
            uint32_t a[2][4], b[4][2];
#pragma unroll
            for (int mf = 0; mf < 2; mf++) {
                int mr = warp * 32 + mf * 16 + (lane >> 2);
                a[mf][0] = *(const uint32_t*)&As[mr][kq];
                a[mf][1] = *(const uint32_t*)&As[mr + 8][kq];
                a[mf][2] = *(const uint32_t*)&As[mr][kq + 8];
                a[mf][3] = *(const uint32_t*)&As[mr + 8][kq + 8];
            }
#pragma unroll
            for (int nf = 0; nf < 4; nf++) {
                int nc = nf * 8 + (lane >> 2);
                b[nf][0] = *(const uint32_t*)&Bs[nc][kq];
                b[nf][1] = *(const uint32_t*)&Bs[nc][kq + 8];
            }
#pragma unroll
            for (int mf = 0; mf < 2; mf++)
#pragma unroll
                for (int nf = 0; nf < 4; nf++)
                    mma_f16(c[mf][nf], a[mf], b[nf]);
        }
        __syncthreads();
    }

#pragma unroll
    for (int mf = 0; mf < 2; mf++) {
        int r = row0 + warp * 32 + mf * 16 + (lane >> 2);
#pragma unroll
        for (int nf = 0; nf < 4; nf++) {
            int ce = nf * 8 + 2 * (lane & 3);
            float bx = bias[ce], by = bias[ce + 1];
            float2 s0, s1;
            s0.x = c[mf][nf][0] + bx; s0.y = c[mf][nf][1] + by;
            s1.x = c[mf][nf][2] + bx; s1.y = c[mf][nf][3] + by;
            *(float2*)(C + (size_t)r * HID + ce) = s0;
            *(float2*)(C + (size_t)(r + 8) * HID + ce) = s1;
        }
    }
}

/* ------------------------- tf32 tensor-core GEMM 128x64x32 ------------------------- */
__device__ __forceinline__ uint32_t f2tf(float x) {
    uint32_t u;
    asm("cvt.rna.tf32.f32 %0, %1;" : "=r"(u) : "f"(x));
    return u;
}
__device__ __forceinline__ void mma_tf32(float* c, const uint32_t* a, const uint32_t* b) {
    asm volatile(
        "mma.sync.aligned.m16n8k8.row.col.f32.tf32.tf32.f32 "
        "{%0,%1,%2,%3}, {%4,%5,%6,%7}, {%8,%9}, {%0,%1,%2,%3};"
        : "+f"(c[0]), "+f"(c[1]), "+f"(c[2]), "+f"(c[3])
        : "r"(a[0]), "r"(a[1]), "r"(a[2]), "r"(a[3]), "r"(b[0]), "r"(b[1]));
}

template<bool BIAS, bool RELU, bool RES, bool DUAL>
__global__ __launch_bounds__(256) void gemmt_k(const float* __restrict__ A,
                                               const float* __restrict__ B,
                                               const float* __restrict__ bias,
                                               const float* __restrict__ res,
                                               float* __restrict__ C,
                                               int K, int ldb, int ldc,
                                               const float* __restrict__ B2 = nullptr,
                                               const float* __restrict__ bias2 = nullptr,
                                               float* __restrict__ C2 = nullptr) {
    constexpr int BM = 128, BN = 64, BK = 32;
    __shared__ uint32_t As[BM][36];
    __shared__ uint32_t Bs[BK][72];
    const int tid = threadIdx.x;
    const int lane = tid & 31;
    const int warp = tid >> 5;
    const int wm = warp >> 1;
    const int wn = warp & 1;
    const int row0 = blockIdx.x * BM;
    const int lda = K;
    int col0;
    if (DUAL) {
        int half = gridDim.y / 2;
        int y = blockIdx.y;
        if (y >= half) { B = B2; bias = bias2; C = C2; y -= half; }
        col0 = y * BN;
    } else {
        col0 = blockIdx.y * BN;
    }

    float c[2][4][4];
#pragma unroll
    for (int mf = 0; mf < 2; mf++)
#pragma unroll
        for (int nf = 0; nf < 4; nf++)
#pragma unroll
            for (int i = 0; i < 4; i++) c[mf][nf][i] = 0.f;

    for (int k0 = 0; k0 < K; k0 += BK) {
#pragma unroll
        for (int it = 0; it < 4; it++) {
            int i = tid + it * 256;
            int r = i >> 3, c4 = i & 7;
            float4 v = *(const float4*)(A + (size_t)(row0 + r) * lda + k0 + c4 * 4);
            uint4 u;
            u.x = f2tf(v.x); u.y = f2tf(v.y); u.z = f2tf(v.z); u.w = f2tf(v.w);
            *(uint4*)&As[r][c4 * 4] = u;
        }
#pragma unroll
        for (int it = 0; it < 2; it++) {
            int i = tid + it * 256;
            int r = i >> 4, c4 = i & 15;
            float4 v = *(const float4*)(B + (size_t)(k0 + r) * ldb + col0 + c4 * 4);
            uint4 u;
            u.x = f2tf(v.x); u.y = f2tf(v.y); u.z = f2tf(v.z); u.w = f2tf(v.w);
            *(uint4*)&Bs[r][c4 * 4] = u;
        }
        __syncthreads();
#pragma unroll
        for (int ks = 0; ks < 4; ks++) {
            int kk = ks * 8 + (lane & 3);
            uint32_t a[2][4], b[4][2];
#pragma unroll
            for (int mf = 0; mf < 2; mf++) {
                int mr = wm * 32 + mf * 16 + (lane >> 2);
                a[mf][0] = As[mr][kk];
                a[mf][1] = As[mr + 8][kk];
                a[mf][2] = As[mr][kk + 4];
                a[mf][3] = As[mr + 8][kk + 4];
            }
#pragma unroll
            for (int nf = 0; nf < 4; nf++) {
                int nc = wn * 32 + nf * 8 + (lane >> 2);
                b[nf][0] = Bs[kk][nc];
                b[nf][1] = Bs[kk + 4][nc];
            }
#pragma unroll
            for (int mf = 0; mf < 2; mf++)
#pragma unroll
                for (int nf = 0; nf < 4; nf++)
                    mma_tf32(c[mf][nf], a[mf], b[nf]);
        }
        __syncthreads();
    }

#pragma unroll
    for (int mf = 0; mf < 2; mf++) {
        int r = row0 + wm * 32 + mf * 16 + (lane >> 2);
#pragma unroll
        for (int nf = 0; nf < 4; nf++) {
            int ce = col0 + wn * 32 + nf * 8 + 2 * (lane & 3);
            float bx = 0.f, by = 0.f;
            if (BIAS) { bx = bias[ce]; by = bias[ce + 1]; }
            float v0 = c[mf][nf][0] + bx, v1 = c[mf][nf][1] + by;
            float v2 = c[mf][nf][2] + bx, v3 = c[mf][nf][3] + by;
            if (RELU) {
                v0 = fmaxf(v0, 0.f); v1 = fmaxf(v1, 0.f);
                v2 = fmaxf(v2, 0.f); v3 = fmaxf(v3, 0.f);
            }
            if (RES) {
                float2 r0 = *(const float2*)(res + (size_t)r * ldc + ce);
                float2 r1 = *(const float2*)(res + (size_t)(r + 8) * ldc + ce);
                v0 += r0.x; v1 += r0.y; v2 += r1.x; v3 += r1.y;
            }
            float2 s0; s0.x = v0; s0.y = v1;
            float2 s1; s1.x = v2; s1.y = v3;
            *(float2*)(C + (size_t)r * ldc + ce) = s0;
            *(float2*)(C + (size_t)(r + 8) * ldc + ce) = s1;
        }
    }
}

/* ------------------------- per-(b,g) attention, flash-style ------------------------- */
__global__ __launch_bounds__(192) void attn_k(const float* __restrict__ k_w) {
    int g = blockIdx.x, b = blockIdx.y;
    __shared__ float kx_s[NPRI * HD];
    int tid = threadIdx.x;
    for (int i = tid; i < NPRI * HD; i += 192) {
        int n = i / HD, d = i % HD;
        kx_s[i] = g_feat[(size_t)(b * NPRI + n) * HID + g * HD + d];
    }
    __syncthreads();

    float qt[HD];
    {
        float qr[HD];
#pragma unroll
        for (int d = 0; d < HD; d++)
            qr[d] = g_q[(size_t)(b * NPRI + tid) * HID + g * HD + d];
#pragma unroll
        for (int e = 0; e < HD; e++) {
            float s = 0.f;
#pragma unroll
            for (int d = 0; d < HD; d++) s += k_w[e * HD + d] * qr[d];
            qt[e] = s * 0.17677669529663687f;
        }
    }
    float acc[HD];
#pragma unroll
    for (int d = 0; d < HD; d++) acc[d] = 0.f;
    float mx = -INFINITY, ls = 0.f;
    for (int mkey = 0; mkey < NPRI; mkey++) {
        const float* kr = &kx_s[mkey * HD];
        float s = 0.f;
#pragma unroll
        for (int e = 0; e < HD; e++) s += qt[e] * kr[e];
        float mn = fmaxf(mx, s);
        float corr = expf(mx - mn);
        float p = expf(s - mn);
        ls = ls * corr + p;
#pragma unroll
        for (int d = 0; d < HD; d++) acc[d] = acc[d] * corr + p * kr[d];
        mx = mn;
    }
    float inv = 1.f / ls;
#pragma unroll
    for (int d = 0; d < HD; d++)
        g_ctx[(size_t)(b * NPRI + tid) * HID + g * HD + d] = acc[d] * inv;
}

/* ------------------------- final heads + output assembly ------------------------- */
__global__ void head_k(const float* __restrict__ cls_w, const float* __restrict__ cls_b,
                       const float* __restrict__ reg_w, const float* __restrict__ reg_b,
                       const float* __restrict__ priors, float* __restrict__ out) {
    __shared__ float sc[3][HID], sr[3][HID];
    int m0 = blockIdx.x * 3;
    int tid = threadIdx.y * 76 + threadIdx.x;
    for (int i = tid; i < 3 * HID; i += 228) {
        int r = i / HID, c = i % HID;
        sc[r][c] = g_clsf[(size_t)(m0 + r) * HID + c];
        sr[r][c] = g_regf[(size_t)(m0 + r) * HID + c];
    }
    __syncthreads();
    int r = threadIdx.y, col = threadIdx.x;
    int m = m0 + r;
    float v;
    if (col < 2) {
        v = cls_b[col];
        for (int e = 0; e < HID; e++) v += sc[r][e] * cls_w[e * 2 + col];
    } else {
        int jj = col - 2;
        v = reg_b[jj] + priors[(size_t)m * PRI_DIM + col];
        for (int e = 0; e < HID; e++) v += sr[r][e] * reg_w[e * 74 + jj];
    }
    out[(size_t)m * OUT_COLS + col] = v;
}

/* ------------------------- host driver ------------------------- */
extern "C" void kernel_launch(void* const* d_in, const int* in_sizes, int n_in,
                              void* d_out, int out_size) {
    const float* feat0   = (const float*)d_in[0];
    const float* feat1   = (const float*)d_in[1];
    const float* feat2   = (const float*)d_in[2];
    const float* priors  = (const float*)d_in[3];
    const float* z_emb   = (const float*)d_in[4];
    const float* gather_w= (const float*)d_in[5];
    const float* gather_b= (const float*)d_in[6];
    const float* q_w     = (const float*)d_in[7];
    const float* k_w     = (const float*)d_in[8];
    const float* ch_w1   = (const float*)d_in[9];
    const float* ch_b1   = (const float*)d_in[10];
    const float* ch_w2   = (const float*)d_in[11];
    const float* ch_b2   = (const float*)d_in[12];
    const float* reg_m_w = (const float*)d_in[13];
    const float* reg_m_b = (const float*)d_in[14];
    const float* cls_m_w = (const float*)d_in[15];
    const float* cls_m_b = (const float*)d_in[16];
    const float* reg_w   = (const float*)d_in[17];
    const float* reg_b   = (const float*)d_in[18];
    const float* cls_w   = (const float*)d_in[19];
    const float* cls_b   = (const float*)d_in[20];
    float* out = (float*)d_out;

    __half *p_nhwc0, *p_nhwc1, *p_nhwc2;
    float *p_feat, *p_q, *p_ctx, *p_h, *p_fc, *p_clsf, *p_regf;
    cudaGetSymbolAddress((void**)&p_nhwc0, g_nhwc0);
    cudaGetSymbolAddress((void**)&p_nhwc1, g_nhwc1);
    cudaGetSymbolAddress((void**)&p_nhwc2, g_nhwc2);
    cudaGetSymbolAddress((void**)&p_feat, g_feat);
    cudaGetSymbolAddress((void**)&p_q, g_q);
    cudaGetSymbolAddress((void**)&p_ctx, g_ctx);
    cudaGetSymbolAddress((void**)&p_h, g_h);
    cudaGetSymbolAddress((void**)&p_fc, g_fc);
    cudaGetSymbolAddress((void**)&p_clsf, g_clsf);
    cudaGetSymbolAddress((void**)&p_regf, g_regf);

    dim3 tb(32, 8);
    transpose_k<<<dim3(8,   2, BATCH), tb>>>(feat0, p_nhwc0, 64, 250);
    transpose_k<<<dim3(32,  2, BATCH), tb>>>(feat1, p_nhwc1, 64, 1000);
    transpose_k<<<dim3(125, 2, BATCH), tb>>>(feat2, p_nhwc2, 64, 4000);

    convw_k<<<(GRP * 32 * 384 + 255) / 256, 256>>>(gather_w);
    meta_k<<<(MS + 255) / 256, 256>>>(priors, z_emb);
    gather_k<<<MS / 8, dim3(32, 8)>>>();

    /* gather_fc fp16 TC, gridDim.y = group */
    gemmg_h<<<dim3(M_ROWS / 256, GRP), 256>>>(gather_b, p_feat);

    /* q = feat @ q_w (tf32 TC) */
    gemmt_k<false, false, false, false><<<dim3(M_ROWS / 128, 3), 256>>>(
        p_feat, q_w, nullptr, nullptr, p_q, HID, HID, HID);

    attn_k<<<dim3(GRP, BATCH), 192>>>(k_w);

    /* channel MLP (tf32 TC) */
    gemmt_k<true, true, false, false><<<dim3(M_ROWS / 128, 6), 256>>>(
        p_ctx, ch_w1, ch_b1, nullptr, p_h, HID, 2 * HID, 2 * HID);
    gemmt_k<true, false, true, false><<<dim3(M_ROWS / 128, 3), 256>>>(
        p_h, ch_w2, ch_b2, p_feat, p_fc, 2 * HID, HID, HID);

    /* heads merged (tf32 TC, DUAL) */
    gemmt_k<true, true, false, true><<<dim3(M_ROWS / 128, 6), 256>>>(
        p_fc, cls_m_w, cls_m_b, nullptr, p_clsf, HID, HID, HID,
        reg_m_w, reg_m_b, p_regf);

    head_k<<<M_ROWS / 3, dim3(76, 3)>>>(cls_w, cls_b, reg_w, reg_b, priors, out);
}